// round 2
// baseline (speedup 1.0000x reference)
#include <cuda_runtime.h>
#include <cuda_bf16.h>
#include <math.h>
#include <stdint.h>

#define NN   4096
#define HH   4
#define NW   (NN/32)     // 128 words per adjacency row

// ---------------- device scratch ----------------
__device__ uint32_t g_adjbits[NN * NW];          // 2 MB packed adjacency
__device__ float    g_h1 [NN * 512];             // x @ W1
__device__ float    g_x1 [NN * 512];             // GAT1 out
__device__ float    g_t1 [NN * 64];              // x1 @ lw1 + b
__device__ float    g_x2 [NN * 64];              // bn_elu
__device__ float    g_h2 [NN * 128];             // x2 @ W2
__device__ float    g_x3 [NN * 128];             // GAT2 out
__device__ float    g_t2 [NN * 16];              // x3 @ lw2 + b
__device__ float    g_es [HH * NN];
__device__ float    g_ed [HH * NN];
__device__ float    g_A1 [HH * NN];
__device__ float    g_A2 [HH * NN];
__device__ float    g_E1 [HH * NN];
__device__ float    g_E2 [HH * NN];
__device__ float    g_Mh [HH];

// ---------------- pack adjacency to bitmask ----------------
__global__ void pack_adj_kernel(const int* __restrict__ adj, uint32_t* __restrict__ bits) {
    int row  = blockIdx.x;
    int warp = threadIdx.x >> 5;
    int lane = threadIdx.x & 31;
    for (int w = warp; w < NW; w += 32) {
        int v = adj[(size_t)row * NN + w * 32 + lane];
        unsigned m = __ballot_sync(0xffffffffu, v > 0);
        if (lane == 0) bits[row * NW + w] = m;
    }
}

// ---------------- generic fp32 GEMM: C[M,N] = A[M,K] @ B[K,N] (+bias) ----------------
// BM=64, BN=64, BK=16, 256 threads, 4x4 per thread. Requires M%64==0, K%16==0, N%4==0.
__global__ void __launch_bounds__(256) gemm_kernel(
    const float* __restrict__ A, const float* __restrict__ B,
    const float* __restrict__ bias, float* __restrict__ C,
    int M, int Nc, int K)
{
    __shared__ float As[16][68];
    __shared__ float Bs[16][68];
    int tx = threadIdx.x & 15, ty = threadIdx.x >> 4;
    int m0 = blockIdx.y * 64, n0 = blockIdx.x * 64;
    float acc[4][4] = {};

    for (int k0 = 0; k0 < K; k0 += 16) {
        { // load A tile (64x16) as float4, store transposed
            int m  = threadIdx.x >> 2;
            int kv = threadIdx.x & 3;
            float4 a = *(const float4*)&A[(size_t)(m0 + m) * K + k0 + kv * 4];
            As[kv*4+0][m] = a.x; As[kv*4+1][m] = a.y;
            As[kv*4+2][m] = a.z; As[kv*4+3][m] = a.w;
        }
        { // load B tile (16x64)
            int k  = threadIdx.x >> 4;
            int nv = threadIdx.x & 15;
            int n  = n0 + nv * 4;
            float4 b = make_float4(0.f, 0.f, 0.f, 0.f);
            if (n < Nc) b = *(const float4*)&B[(size_t)(k0 + k) * Nc + n];
            *(float4*)&Bs[k][nv*4] = b;
        }
        __syncthreads();
        #pragma unroll
        for (int k = 0; k < 16; k++) {
            float4 a4 = *(const float4*)&As[k][ty*4];
            float4 b4 = *(const float4*)&Bs[k][tx*4];
            float av[4] = {a4.x, a4.y, a4.z, a4.w};
            float bv[4] = {b4.x, b4.y, b4.z, b4.w};
            #pragma unroll
            for (int i = 0; i < 4; i++)
                #pragma unroll
                for (int j = 0; j < 4; j++)
                    acc[i][j] += av[i] * bv[j];
        }
        __syncthreads();
    }
    int col = n0 + tx * 4;
    if (col < Nc) {
        float4 bv = make_float4(0.f,0.f,0.f,0.f);
        if (bias) bv = *(const float4*)&bias[col];
        #pragma unroll
        for (int i = 0; i < 4; i++) {
            int row = m0 + ty * 4 + i;
            float4 o;
            o.x = acc[i][0] + bv.x; o.y = acc[i][1] + bv.y;
            o.z = acc[i][2] + bv.z; o.w = acc[i][3] + bv.w;
            *(float4*)&C[(size_t)row * Nc + col] = o;
        }
    }
}

// ---------------- es/ed: per-node per-head dot products ----------------
// h: [N][H*F], as/ad: [H][F]; one block per node, warp = head
__global__ void esed_kernel(const float* __restrict__ h,
                            const float* __restrict__ as_, const float* __restrict__ ad_,
                            float* __restrict__ es, float* __restrict__ ed, int F)
{
    int i = blockIdx.x;
    int w = threadIdx.x >> 5, lane = threadIdx.x & 31;
    float s = 0.f, d = 0.f;
    for (int f = lane; f < F; f += 32) {
        float hv = h[(size_t)i * (HH * F) + w * F + f];
        s += hv * as_[w * F + f];
        d += hv * ad_[w * F + f];
    }
    #pragma unroll
    for (int off = 16; off; off >>= 1) {
        s += __shfl_xor_sync(0xffffffffu, s, off);
        d += __shfl_xor_sync(0xffffffffu, d, off);
    }
    if (lane == 0) { es[w * NN + i] = s; ed[w * NN + i] = d; }
}

// ---------------- per-head max of ed ----------------
__global__ void headmax_kernel(const float* __restrict__ ed, float* __restrict__ Mh) {
    int h = blockIdx.x;
    __shared__ float red[256];
    float m = -1e30f;
    for (int j = threadIdx.x; j < NN; j += 256) m = fmaxf(m, ed[h * NN + j]);
    red[threadIdx.x] = m; __syncthreads();
    for (int s = 128; s; s >>= 1) {
        if (threadIdx.x < s) red[threadIdx.x] = fmaxf(red[threadIdx.x], red[threadIdx.x + s]);
        __syncthreads();
    }
    if (threadIdx.x == 0) Mh[h] = red[0];
}

// ---------------- A1/A2/E1/E2 factors ----------------
// m_i = leaky(es_i + Mh) (upper bound of row max); w_ij = adj * (s>=0 ? A1_i E1_j : A2_i E2_j)
__global__ void prep_kernel(const float* __restrict__ es, const float* __restrict__ ed,
                            const float* __restrict__ Mh,
                            float* __restrict__ A1, float* __restrict__ A2,
                            float* __restrict__ E1, float* __restrict__ E2)
{
    int idx = blockIdx.x * blockDim.x + threadIdx.x;   // h*NN + j
    if (idx >= HH * NN) return;
    int h = idx >> 12;
    float edv = ed[idx];
    E1[idx] = expf(edv);
    E2[idx] = expf(0.2f * edv);
    float esv  = es[idx];
    float smax = esv + Mh[h];
    float m    = (smax >= 0.f) ? smax : 0.2f * smax;
    A1[idx] = expf(esv - m);
    A2[idx] = expf(0.2f * esv - m);
}

// ---------------- fused masked-softmax attention aggregation ----------------
// out[i, head*F + f] = (1/Z_i) * sum_j w_ij * h[j, head*F + f]
template<int F>
__global__ void __launch_bounds__(256) attn_kernel(
    const float* __restrict__ hbuf,          // [N][H*F]
    const uint32_t* __restrict__ adjbits,    // [N][NW]
    const float* __restrict__ es, const float* __restrict__ ed,
    const float* __restrict__ A1g, const float* __restrict__ A2g,
    const float* __restrict__ E1g, const float* __restrict__ E2g,
    float* __restrict__ out)                 // [N][H*F]
{
    constexpr int TI  = 64;
    constexpr int JB  = 32;
    constexpr int FT  = F / 4;            // threads along f (32 or 8)
    constexpr int RPT = TI * FT / 256;    // rows/thread in accumulate phase (8 or 2)
    constexpr int LDH = HH * F;

    const int head = blockIdx.y;
    const int i0   = blockIdx.x * TI;
    const int tid  = threadIdx.x;
    const int lane = tid & 31, warp = tid >> 5;

    __shared__ float h_s[JB][F + 4];
    __shared__ float w_s[JB][TI + 1];
    __shared__ float es_s[TI], A1_s[TI], A2_s[TI], z_s[TI];

    if (tid < TI) {
        es_s[tid] = es [head * NN + i0 + tid];
        A1_s[tid] = A1g[head * NN + i0 + tid];
        A2_s[tid] = A2g[head * NN + i0 + tid];
    }

    float acc[RPT][4];
    #pragma unroll
    for (int k = 0; k < RPT; k++) { acc[k][0]=0.f; acc[k][1]=0.f; acc[k][2]=0.f; acc[k][3]=0.f; }
    float zpriv[8] = {0.f,0.f,0.f,0.f,0.f,0.f,0.f,0.f};

    const int fthr   = tid % FT;
    const int rbase2 = (tid / FT) * RPT;   // accumulate-phase rows
    const int r1base = warp * 8;           // w-phase rows (8 per warp)

    __syncthreads();

    for (int jb = 0; jb < NN / JB; jb++) {
        const int j0 = jb * JB;
        // phase 0: stage h tile [JB][F]
        constexpr int NV = JB * F / 1024;  // float4s per thread (4 or 1)
        #pragma unroll
        for (int v = 0; v < NV; v++) {
            int idx = v * 256 + tid;            // over [JB][F/4]
            int j   = idx / (F / 4);
            int f4  = idx % (F / 4);
            float4 hv = *(const float4*)&hbuf[(size_t)(j0 + j) * LDH + head * F + f4 * 4];
            *(float4*)&h_s[j][f4 * 4] = hv;
        }
        // phase 1: build w tile [JB][TI]; thread column j=lane, 8 rows per warp
        {
            int jg = j0 + lane;
            float edv = ed [head * NN + jg];
            float e1  = E1g[head * NN + jg];
            float e2  = E2g[head * NN + jg];
            #pragma unroll
            for (int k = 0; k < 8; k++) {
                int r = r1base + k;
                uint32_t word = adjbits[(size_t)(i0 + r) * NW + jb];
                float s = es_s[r] + edv;
                float w = (s >= 0.f) ? A1_s[r] * e1 : A2_s[r] * e2;
                w = ((word >> lane) & 1u) ? w : 0.f;
                zpriv[k] += w;
                w_s[lane][r] = w;
            }
        }
        __syncthreads();
        // phase 2: rank-JB update, pure FFMA
        #pragma unroll 4
        for (int j = 0; j < JB; j++) {
            float4 hv = *(const float4*)&h_s[j][fthr * 4];
            #pragma unroll
            for (int k = 0; k < RPT; k++) {
                float wv = w_s[j][rbase2 + k];
                acc[k][0] += wv * hv.x; acc[k][1] += wv * hv.y;
                acc[k][2] += wv * hv.z; acc[k][3] += wv * hv.w;
            }
        }
        __syncthreads();
    }

    // Z reduction: lanes of each warp hold partial sums over j for rows r1base..r1base+7
    #pragma unroll
    for (int k = 0; k < 8; k++) {
        float z = zpriv[k];
        #pragma unroll
        for (int off = 16; off; off >>= 1) z += __shfl_xor_sync(0xffffffffu, z, off);
        if (lane == 0) z_s[r1base + k] = z;
    }
    __syncthreads();

    #pragma unroll
    for (int k = 0; k < RPT; k++) {
        int r = rbase2 + k;
        float zi = 1.f / z_s[r];
        float4 o;
        o.x = acc[k][0] * zi; o.y = acc[k][1] * zi;
        o.z = acc[k][2] * zi; o.w = acc[k][3] * zi;
        *(float4*)&out[(size_t)(i0 + r) * LDH + head * F + fthr * 4] = o;
    }
}

// ---------------- BatchNorm (over rows) + ELU ----------------
// X: [4096][C], one block per column
__global__ void bnelu_kernel(const float* __restrict__ X,
                             const float* __restrict__ gamma, const float* __restrict__ beta,
                             float* __restrict__ Y, int C)
{
    int c = blockIdx.x;
    int t = threadIdx.x;
    float v[16];
    float s = 0.f, sq = 0.f;
    #pragma unroll
    for (int k = 0; k < 16; k++) {
        float x = X[(size_t)(t + k * 256) * C + c];
        v[k] = x; s += x; sq += x * x;
    }
    __shared__ float rs[256], rq[256];
    rs[t] = s; rq[t] = sq; __syncthreads();
    for (int o = 128; o; o >>= 1) {
        if (t < o) { rs[t] += rs[t + o]; rq[t] += rq[t + o]; }
        __syncthreads();
    }
    float mean = rs[0] * (1.f / NN);
    float var  = rq[0] * (1.f / NN) - mean * mean;
    float scale = rsqrtf(var + 1e-5f);
    float gm = gamma[c], bt = beta[c];
    #pragma unroll
    for (int k = 0; k < 16; k++) {
        float y = (v[k] - mean) * scale * gm + bt;
        y = (y > 0.f) ? y : expm1f(y);
        Y[(size_t)(t + k * 256) * C + c] = y;
    }
}

// ---------------- host ----------------
static inline void* sym(const void* s) { void* p = nullptr; cudaGetSymbolAddress(&p, s); return p; }

extern "C" void kernel_launch(void* const* d_in, const int* in_sizes, int n_in,
                              void* d_out, int out_size)
{
    const float* x   = (const float*)d_in[0];
    const int*   adj = (const int*)  d_in[1];
    const float* W1  = (const float*)d_in[2];
    const float* a1s = (const float*)d_in[3];
    const float* a1d = (const float*)d_in[4];
    const float* lw1 = (const float*)d_in[5];
    const float* lb1 = (const float*)d_in[6];
    const float* g1  = (const float*)d_in[7];
    const float* be1 = (const float*)d_in[8];
    const float* W2  = (const float*)d_in[9];
    const float* a2s = (const float*)d_in[10];
    const float* a2d = (const float*)d_in[11];
    const float* lw2 = (const float*)d_in[12];
    const float* lb2 = (const float*)d_in[13];
    const float* g2  = (const float*)d_in[14];
    const float* be2 = (const float*)d_in[15];
    float* outp = (float*)d_out;

    uint32_t* adjbits = (uint32_t*)sym(g_adjbits);
    float* h1 = (float*)sym(g_h1);
    float* x1 = (float*)sym(g_x1);
    float* t1 = (float*)sym(g_t1);
    float* x2 = (float*)sym(g_x2);
    float* h2 = (float*)sym(g_h2);
    float* x3 = (float*)sym(g_x3);
    float* t2 = (float*)sym(g_t2);
    float* es = (float*)sym(g_es);
    float* ed = (float*)sym(g_ed);
    float* A1 = (float*)sym(g_A1);
    float* A2 = (float*)sym(g_A2);
    float* E1 = (float*)sym(g_E1);
    float* E2 = (float*)sym(g_E2);
    float* Mh = (float*)sym(g_Mh);

    pack_adj_kernel<<<NN, 1024>>>(adj, adjbits);

    // ----- layer 1 -----
    gemm_kernel<<<dim3(512/64, NN/64), 256>>>(x, W1, nullptr, h1, NN, 512, 512);
    esed_kernel<<<NN, 128>>>(h1, a1s, a1d, es, ed, 128);
    headmax_kernel<<<HH, 256>>>(ed, Mh);
    prep_kernel<<<(HH*NN)/256, 256>>>(es, ed, Mh, A1, A2, E1, E2);
    attn_kernel<128><<<dim3(NN/64, HH), 256>>>(h1, adjbits, es, ed, A1, A2, E1, E2, x1);

    gemm_kernel<<<dim3(1, NN/64), 256>>>(x1, lw1, lb1, t1, NN, 64, 512);
    bnelu_kernel<<<64, 256>>>(t1, g1, be1, x2, 64);

    // ----- layer 2 -----
    gemm_kernel<<<dim3(2, NN/64), 256>>>(x2, W2, nullptr, h2, NN, 128, 64);
    esed_kernel<<<NN, 128>>>(h2, a2s, a2d, es, ed, 32);
    headmax_kernel<<<HH, 256>>>(ed, Mh);
    prep_kernel<<<(HH*NN)/256, 256>>>(es, ed, Mh, A1, A2, E1, E2);
    attn_kernel<32><<<dim3(NN/64, HH), 256>>>(h2, adjbits, es, ed, A1, A2, E1, E2, x3);

    gemm_kernel<<<dim3(1, NN/64), 256>>>(x3, lw2, lb2, t2, NN, 16, 128);
    bnelu_kernel<<<16, 256>>>(t2, g2, be2, outp, 16);
}

// round 7
// speedup vs baseline: 1.2427x; 1.2427x over previous
#include <cuda_runtime.h>
#include <cuda_bf16.h>
#include <math.h>
#include <stdint.h>

#define NN   4096
#define HH   4
#define NW   (NN/32)     // 128 words per adjacency row

// ---------------- device scratch ----------------
__device__ uint32_t g_adjbits[NN * NW];          // 2 MB packed adjacency
__device__ float    g_h1 [NN * 512];             // x @ W1
__device__ float    g_x1 [NN * 512];             // GAT1 out
__device__ float    g_t1 [NN * 64];              // x1 @ lw1 + b
__device__ float    g_x2 [NN * 64];              // bn_elu
__device__ float    g_h2 [NN * 128];             // x2 @ W2
__device__ float    g_x3 [NN * 128];             // GAT2 out
__device__ float    g_t2 [NN * 16];              // x3 @ lw2 + b
__device__ float    g_es [HH * NN];
__device__ float    g_ed [HH * NN];
__device__ float    g_A1 [HH * NN];
__device__ float    g_A2 [HH * NN];
__device__ float    g_E1 [HH * NN];
__device__ float    g_E2 [HH * NN];
__device__ float    g_Mh [HH];

// ---------------- small helpers ----------------
__device__ __forceinline__ uint32_t f2tf(float x) {
    uint32_t r;
    asm("cvt.rna.tf32.f32 %0, %1;" : "=r"(r) : "f"(x));
    return r;
}

// 3xTF32 split: x ~= hi + lo, both tf32-representable
__device__ __forceinline__ void split_tf32(float x, uint32_t& hi, uint32_t& lo) {
    hi = f2tf(x);
    float r = x - __uint_as_float(hi);
    lo = f2tf(r);
}

__device__ __forceinline__ void mma_tf32(float c[4],
    const uint32_t a[4], uint32_t b0, uint32_t b1)
{
    asm volatile(
        "mma.sync.aligned.m16n8k8.row.col.f32.tf32.tf32.f32 "
        "{%0,%1,%2,%3}, {%4,%5,%6,%7}, {%8,%9}, {%0,%1,%2,%3};"
        : "+f"(c[0]), "+f"(c[1]), "+f"(c[2]), "+f"(c[3])
        : "r"(a[0]), "r"(a[1]), "r"(a[2]), "r"(a[3]), "r"(b0), "r"(b1));
}

// ---------------- pack adjacency to bitmask ----------------
__global__ void pack_adj_kernel(const int* __restrict__ adj, uint32_t* __restrict__ bits) {
    int row  = blockIdx.x;
    int warp = threadIdx.x >> 5;
    int lane = threadIdx.x & 31;
    for (int w = warp; w < NW; w += 32) {
        int v = adj[(size_t)row * NN + w * 32 + lane];
        unsigned m = __ballot_sync(0xffffffffu, v > 0);
        if (lane == 0) bits[row * NW + w] = m;
    }
}

// ---------------- 3xTF32 tensor-core GEMM: C[M,Nc] = A[M,K] @ B[K,Nc] (+bias) ----------------
// BM=64, BN=64, BK=32, 256 threads (8 warps). Requires M%64==0, Nc%64==0, K%32==0.
__global__ void __launch_bounds__(256) gemm_tf32x3_kernel(
    const float* __restrict__ A, const float* __restrict__ B,
    const float* __restrict__ bias, float* __restrict__ C,
    int M, int Nc, int K)
{
    __shared__ uint32_t Ah[64 * 36], Al[64 * 36];
    __shared__ uint32_t Bh[32 * 72], Bl[32 * 72];

    const int tid  = threadIdx.x;
    const int lane = tid & 31, warp = tid >> 5;
    const int wm = warp & 1;
    const int wn = warp >> 1;
    const int m0 = blockIdx.y * 64, n0 = blockIdx.x * 64;

    float acc[2][2][4] = {};

    for (int k0 = 0; k0 < K; k0 += 32) {
        // stage A tile 64x32 -> split tf32
        #pragma unroll
        for (int v = 0; v < 2; v++) {
            int idx = v * 256 + tid;     // 64 x 8 float4
            int m = idx >> 3, kv = idx & 7;
            float4 a = *(const float4*)&A[(size_t)(m0 + m) * K + k0 + kv * 4];
            uint4 uh, ul;
            split_tf32(a.x, uh.x, ul.x); split_tf32(a.y, uh.y, ul.y);
            split_tf32(a.z, uh.z, ul.z); split_tf32(a.w, uh.w, ul.w);
            *(uint4*)&Ah[m * 36 + kv * 4] = uh;
            *(uint4*)&Al[m * 36 + kv * 4] = ul;
        }
        // stage B tile 32x64 -> split tf32
        #pragma unroll
        for (int v = 0; v < 2; v++) {
            int idx = v * 256 + tid;     // 32 x 16 float4
            int k = idx >> 4, nv = idx & 15;
            float4 b = *(const float4*)&B[(size_t)(k0 + k) * Nc + n0 + nv * 4];
            uint4 uh, ul;
            split_tf32(b.x, uh.x, ul.x); split_tf32(b.y, uh.y, ul.y);
            split_tf32(b.z, uh.z, ul.z); split_tf32(b.w, uh.w, ul.w);
            *(uint4*)&Bh[k * 72 + nv * 4] = uh;
            *(uint4*)&Bl[k * 72 + nv * 4] = ul;
        }
        __syncthreads();

        #pragma unroll
        for (int ks = 0; ks < 4; ks++) {
            const int kk = ks * 8;
            uint32_t ah[2][4], al[2][4];
            #pragma unroll
            for (int mt = 0; mt < 2; mt++) {
                int r = 32 * wm + 16 * mt + (lane >> 2);
                int c = kk + (lane & 3);
                ah[mt][0] = Ah[r * 36 + c];       al[mt][0] = Al[r * 36 + c];
                ah[mt][1] = Ah[(r + 8) * 36 + c]; al[mt][1] = Al[(r + 8) * 36 + c];
                ah[mt][2] = Ah[r * 36 + c + 4];   al[mt][2] = Al[r * 36 + c + 4];
                ah[mt][3] = Ah[(r + 8) * 36 + c + 4]; al[mt][3] = Al[(r + 8) * 36 + c + 4];
            }
            #pragma unroll
            for (int nt = 0; nt < 2; nt++) {
                int col = 16 * wn + 8 * nt + (lane >> 2);
                int ro  = (kk + (lane & 3)) * 72 + col;
                uint32_t bh0 = Bh[ro], bh1 = Bh[ro + 4 * 72];
                uint32_t bl0 = Bl[ro], bl1 = Bl[ro + 4 * 72];
                #pragma unroll
                for (int mt = 0; mt < 2; mt++) {
                    mma_tf32(acc[mt][nt], ah[mt], bh0, bh1);
                    mma_tf32(acc[mt][nt], ah[mt], bl0, bl1);
                    mma_tf32(acc[mt][nt], al[mt], bh0, bh1);
                }
            }
        }
        __syncthreads();
    }

    #pragma unroll
    for (int mt = 0; mt < 2; mt++) {
        #pragma unroll
        for (int nt = 0; nt < 2; nt++) {
            int col = n0 + 16 * wn + 8 * nt + 2 * (lane & 3);
            float bx = bias ? bias[col]     : 0.f;
            float by = bias ? bias[col + 1] : 0.f;
            int r0 = m0 + 32 * wm + 16 * mt + (lane >> 2);
            float2 o0 = make_float2(acc[mt][nt][0] + bx, acc[mt][nt][1] + by);
            float2 o1 = make_float2(acc[mt][nt][2] + bx, acc[mt][nt][3] + by);
            *(float2*)&C[(size_t)r0 * Nc + col]       = o0;
            *(float2*)&C[(size_t)(r0 + 8) * Nc + col] = o1;
        }
    }
}

// ---------------- scalar GEMM (final Nc=16) ----------------
__global__ void __launch_bounds__(256) gemm_kernel(
    const float* __restrict__ A, const float* __restrict__ B,
    const float* __restrict__ bias, float* __restrict__ C,
    int M, int Nc, int K)
{
    __shared__ float As[16][68];
    __shared__ float Bs[16][68];
    int tx = threadIdx.x & 15, ty = threadIdx.x >> 4;
    int m0 = blockIdx.y * 64, n0 = blockIdx.x * 64;
    float acc[4][4] = {};

    for (int k0 = 0; k0 < K; k0 += 16) {
        {
            int m  = threadIdx.x >> 2;
            int kv = threadIdx.x & 3;
            float4 a = *(const float4*)&A[(size_t)(m0 + m) * K + k0 + kv * 4];
            As[kv*4+0][m] = a.x; As[kv*4+1][m] = a.y;
            As[kv*4+2][m] = a.z; As[kv*4+3][m] = a.w;
        }
        {
            int k  = threadIdx.x >> 4;
            int nv = threadIdx.x & 15;
            int n  = n0 + nv * 4;
            float4 b = make_float4(0.f, 0.f, 0.f, 0.f);
            if (n < Nc) b = *(const float4*)&B[(size_t)(k0 + k) * Nc + n];
            *(float4*)&Bs[k][nv*4] = b;
        }
        __syncthreads();
        #pragma unroll
        for (int k = 0; k < 16; k++) {
            float4 a4 = *(const float4*)&As[k][ty*4];
            float4 b4 = *(const float4*)&Bs[k][tx*4];
            float av[4] = {a4.x, a4.y, a4.z, a4.w};
            float bv[4] = {b4.x, b4.y, b4.z, b4.w};
            #pragma unroll
            for (int i = 0; i < 4; i++)
                #pragma unroll
                for (int j = 0; j < 4; j++)
                    acc[i][j] += av[i] * bv[j];
        }
        __syncthreads();
    }
    int col = n0 + tx * 4;
    if (col < Nc) {
        float4 bv = make_float4(0.f,0.f,0.f,0.f);
        if (bias) bv = *(const float4*)&bias[col];
        #pragma unroll
        for (int i = 0; i < 4; i++) {
            int row = m0 + ty * 4 + i;
            float4 o;
            o.x = acc[i][0] + bv.x; o.y = acc[i][1] + bv.y;
            o.z = acc[i][2] + bv.z; o.w = acc[i][3] + bv.w;
            *(float4*)&C[(size_t)row * Nc + col] = o;
        }
    }
}

// ---------------- es/ed ----------------
__global__ void esed_kernel(const float* __restrict__ h,
                            const float* __restrict__ as_, const float* __restrict__ ad_,
                            float* __restrict__ es, float* __restrict__ ed, int F)
{
    int i = blockIdx.x;
    int w = threadIdx.x >> 5, lane = threadIdx.x & 31;
    float s = 0.f, d = 0.f;
    for (int f = lane; f < F; f += 32) {
        float hv = h[(size_t)i * (HH * F) + w * F + f];
        s += hv * as_[w * F + f];
        d += hv * ad_[w * F + f];
    }
    #pragma unroll
    for (int off = 16; off; off >>= 1) {
        s += __shfl_xor_sync(0xffffffffu, s, off);
        d += __shfl_xor_sync(0xffffffffu, d, off);
    }
    if (lane == 0) { es[w * NN + i] = s; ed[w * NN + i] = d; }
}

// ---------------- per-head max of ed ----------------
__global__ void headmax_kernel(const float* __restrict__ ed, float* __restrict__ Mh) {
    int h = blockIdx.x;
    __shared__ float red[256];
    float m = -1e30f;
    for (int j = threadIdx.x; j < NN; j += 256) m = fmaxf(m, ed[h * NN + j]);
    red[threadIdx.x] = m; __syncthreads();
    for (int s = 128; s; s >>= 1) {
        if (threadIdx.x < s) red[threadIdx.x] = fmaxf(red[threadIdx.x], red[threadIdx.x + s]);
        __syncthreads();
    }
    if (threadIdx.x == 0) Mh[h] = red[0];
}

// ---------------- A1/A2/E1/E2 factors ----------------
__global__ void prep_kernel(const float* __restrict__ es, const float* __restrict__ ed,
                            const float* __restrict__ Mh,
                            float* __restrict__ A1, float* __restrict__ A2,
                            float* __restrict__ E1, float* __restrict__ E2)
{
    int idx = blockIdx.x * blockDim.x + threadIdx.x;
    if (idx >= HH * NN) return;
    int h = idx >> 12;
    float edv = ed[idx];
    E1[idx] = expf(edv);
    E2[idx] = expf(0.2f * edv);
    float esv  = es[idx];
    float smax = esv + Mh[h];
    float m    = (smax >= 0.f) ? smax : 0.2f * smax;
    A1[idx] = expf(esv - m);
    A2[idx] = expf(0.2f * esv - m);
}

// ---------------- 3xTF32 tensor-core fused masked-softmax attention ----------------
// out[i, head*F + f] = (1/Z_i) * sum_j w_ij * h[j, head*F + f]
template<int F>
__global__ void __launch_bounds__(256) attn_tc3_kernel(
    const float* __restrict__ hbuf,          // [N][H*F]
    const uint32_t* __restrict__ adjbits,    // [N][NW]
    const float* __restrict__ es, const float* __restrict__ ed,
    const float* __restrict__ A1g, const float* __restrict__ A2g,
    const float* __restrict__ E1g, const float* __restrict__ E2g,
    float* __restrict__ out)                 // [N][H*F]
{
    constexpr int TI  = 64;
    constexpr int JB  = 32;
    constexpr int LDH = HH * F;
    constexpr int HS  = F + 8;       // mod 32 == 8: conflict-free B-frag loads
    constexpr int WS  = 36;          // mod 32 == 4: conflict-free A-frag loads
    constexpr int NT  = F / 32;      // n-tiles per warp (4 for F=128, 1 for F=32)

    const int head = blockIdx.y;
    const int i0   = blockIdx.x * TI;
    const int tid  = threadIdx.x;
    const int lane = tid & 31, warp = tid >> 5;
    const int wm   = warp & 1;
    const int wn   = warp >> 1;

    extern __shared__ uint32_t smdyn[];
    uint32_t* h_hi = smdyn;                   // JB*HS
    uint32_t* h_lo = h_hi + JB * HS;
    uint32_t* w_hi = h_lo + JB * HS;          // TI*WS
    uint32_t* w_lo = w_hi + TI * WS;
    float* es_s = (float*)(w_lo + TI * WS);
    float* A1_s = es_s + TI;
    float* A2_s = A1_s + TI;
    float* z_s  = A2_s + TI;

    if (tid < TI) {
        es_s[tid] = es [head * NN + i0 + tid];
        A1_s[tid] = A1g[head * NN + i0 + tid];
        A2_s[tid] = A2g[head * NN + i0 + tid];
    }

    float acc[2][NT][4];
    #pragma unroll
    for (int mt = 0; mt < 2; mt++)
        #pragma unroll
        for (int nt = 0; nt < NT; nt++)
            #pragma unroll
            for (int q = 0; q < 4; q++) acc[mt][nt][q] = 0.f;

    float zpriv[8] = {0.f,0.f,0.f,0.f,0.f,0.f,0.f,0.f};
    const int r1base = warp * 8;

    __syncthreads();

    for (int jb = 0; jb < NN / JB; jb++) {
        const int j0 = jb * JB;
        // phase 0: stage h tile [JB][F] -> split tf32
        constexpr int NV = JB * F / 1024;
        #pragma unroll
        for (int v = 0; v < NV; v++) {
            int idx = v * 256 + tid;
            int j   = idx / (F / 4);
            int f4  = idx % (F / 4);
            float4 hv = *(const float4*)&hbuf[(size_t)(j0 + j) * LDH + head * F + f4 * 4];
            uint4 uh, ul;
            split_tf32(hv.x, uh.x, ul.x); split_tf32(hv.y, uh.y, ul.y);
            split_tf32(hv.z, uh.z, ul.z); split_tf32(hv.w, uh.w, ul.w);
            *(uint4*)&h_hi[j * HS + f4 * 4] = uh;
            *(uint4*)&h_lo[j * HS + f4 * 4] = ul;
        }
        // phase 1: build w tile [TI][JB]; thread column j=lane, 8 rows per warp
        {
            int jg = j0 + lane;
            float edv = ed [head * NN + jg];
            float e1  = E1g[head * NN + jg];
            float e2  = E2g[head * NN + jg];
            #pragma unroll
            for (int k = 0; k < 8; k++) {
                int r = r1base + k;
                uint32_t word = adjbits[(size_t)(i0 + r) * NW + jb];
                float s = es_s[r] + edv;
                float w = (s >= 0.f) ? A1_s[r] * e1 : A2_s[r] * e2;
                w = ((word >> lane) & 1u) ? w : 0.f;
                zpriv[k] += w;
                uint32_t whi, wlo;
                split_tf32(w, whi, wlo);
                w_hi[r * WS + lane] = whi;
                w_lo[r * WS + lane] = wlo;
            }
        }
        __syncthreads();
        // phase 2: C += w @ h via 3xTF32 mma
        #pragma unroll
        for (int ks = 0; ks < 4; ks++) {
            const int kk = ks * 8;
            uint32_t ah[2][4], al[2][4];
            #pragma unroll
            for (int mt = 0; mt < 2; mt++) {
                int r = 32 * wm + 16 * mt + (lane >> 2);
                int c = kk + (lane & 3);
                ah[mt][0] = w_hi[r * WS + c];       al[mt][0] = w_lo[r * WS + c];
                ah[mt][1] = w_hi[(r + 8) * WS + c]; al[mt][1] = w_lo[(r + 8) * WS + c];
                ah[mt][2] = w_hi[r * WS + c + 4];   al[mt][2] = w_lo[r * WS + c + 4];
                ah[mt][3] = w_hi[(r + 8) * WS + c + 4]; al[mt][3] = w_lo[(r + 8) * WS + c + 4];
            }
            #pragma unroll
            for (int nt = 0; nt < NT; nt++) {
                int col = wn * 8 * NT + 8 * nt + (lane >> 2);
                int ro  = (kk + (lane & 3)) * HS + col;
                uint32_t bh0 = h_hi[ro], bh1 = h_hi[ro + 4 * HS];
                uint32_t bl0 = h_lo[ro], bl1 = h_lo[ro + 4 * HS];
                #pragma unroll
                for (int mt = 0; mt < 2; mt++) {
                    mma_tf32(acc[mt][nt], ah[mt], bh0, bh1);
                    mma_tf32(acc[mt][nt], ah[mt], bl0, bl1);
                    mma_tf32(acc[mt][nt], al[mt], bh0, bh1);
                }
            }
        }
        __syncthreads();
    }

    // Z reduction
    #pragma unroll
    for (int k = 0; k < 8; k++) {
        float z = zpriv[k];
        #pragma unroll
        for (int off = 16; off; off >>= 1) z += __shfl_xor_sync(0xffffffffu, z, off);
        if (lane == 0) z_s[r1base + k] = z;
    }
    __syncthreads();

    // epilogue
    #pragma unroll
    for (int mt = 0; mt < 2; mt++) {
        int r0 = 32 * wm + 16 * mt + (lane >> 2);
        int r1 = r0 + 8;
        float zi0 = 1.f / z_s[r0];
        float zi1 = 1.f / z_s[r1];
        #pragma unroll
        for (int nt = 0; nt < NT; nt++) {
            int col = wn * 8 * NT + 8 * nt + 2 * (lane & 3);
            float2 o0 = make_float2(acc[mt][nt][0] * zi0, acc[mt][nt][1] * zi0);
            float2 o1 = make_float2(acc[mt][nt][2] * zi1, acc[mt][nt][3] * zi1);
            *(float2*)&out[(size_t)(i0 + r0) * LDH + head * F + col] = o0;
            *(float2*)&out[(size_t)(i0 + r1) * LDH + head * F + col] = o1;
        }
    }
}

// ---------------- BatchNorm (over rows) + ELU ----------------
__global__ void bnelu_kernel(const float* __restrict__ X,
                             const float* __restrict__ gamma, const float* __restrict__ beta,
                             float* __restrict__ Y, int C)
{
    int c = blockIdx.x;
    int t = threadIdx.x;
    float v[16];
    float s = 0.f, sq = 0.f;
    #pragma unroll
    for (int k = 0; k < 16; k++) {
        float x = X[(size_t)(t + k * 256) * C + c];
        v[k] = x; s += x; sq += x * x;
    }
    __shared__ float rs[256], rq[256];
    rs[t] = s; rq[t] = sq; __syncthreads();
    for (int o = 128; o; o >>= 1) {
        if (t < o) { rs[t] += rs[t + o]; rq[t] += rq[t + o]; }
        __syncthreads();
    }
    float mean = rs[0] * (1.f / NN);
    float var  = rq[0] * (1.f / NN) - mean * mean;
    float scale = rsqrtf(var + 1e-5f);
    float gm = gamma[c], bt = beta[c];
    #pragma unroll
    for (int k = 0; k < 16; k++) {
        float y = (v[k] - mean) * scale * gm + bt;
        y = (y > 0.f) ? y : expm1f(y);
        Y[(size_t)(t + k * 256) * C + c] = y;
    }
}

// ---------------- host ----------------
static inline void* sym(const void* s) { void* p = nullptr; cudaGetSymbolAddress(&p, s); return p; }

// dynamic smem sizes for attn kernels
static constexpr int ATTN_SMEM_128 = (2 * 32 * (128 + 8) + 2 * 64 * 36 + 4 * 64) * 4; // 54272 B
static constexpr int ATTN_SMEM_32  = (2 * 32 * (32 + 8)  + 2 * 64 * 36 + 4 * 64) * 4; // 29696 B

extern "C" void kernel_launch(void* const* d_in, const int* in_sizes, int n_in,
                              void* d_out, int out_size)
{
    const float* x   = (const float*)d_in[0];
    const int*   adj = (const int*)  d_in[1];
    const float* W1  = (const float*)d_in[2];
    const float* a1s = (const float*)d_in[3];
    const float* a1d = (const float*)d_in[4];
    const float* lw1 = (const float*)d_in[5];
    const float* lb1 = (const float*)d_in[6];
    const float* g1  = (const float*)d_in[7];
    const float* be1 = (const float*)d_in[8];
    const float* W2  = (const float*)d_in[9];
    const float* a2s = (const float*)d_in[10];
    const float* a2d = (const float*)d_in[11];
    const float* lw2 = (const float*)d_in[12];
    const float* lb2 = (const float*)d_in[13];
    const float* g2  = (const float*)d_in[14];
    const float* be2 = (const float*)d_in[15];
    float* outp = (float*)d_out;

    uint32_t* adjbits = (uint32_t*)sym(g_adjbits);
    float* h1 = (float*)sym(g_h1);
    float* x1 = (float*)sym(g_x1);
    float* t1 = (float*)sym(g_t1);
    float* x2 = (float*)sym(g_x2);
    float* h2 = (float*)sym(g_h2);
    float* x3 = (float*)sym(g_x3);
    float* t2 = (float*)sym(g_t2);
    float* es = (float*)sym(g_es);
    float* ed = (float*)sym(g_ed);
    float* A1 = (float*)sym(g_A1);
    float* A2 = (float*)sym(g_A2);
    float* E1 = (float*)sym(g_E1);
    float* E2 = (float*)sym(g_E2);
    float* Mh = (float*)sym(g_Mh);

    // opt-in >48KB dynamic smem for the F=128 attention kernel (idempotent, capture-safe)
    cudaFuncSetAttribute(attn_tc3_kernel<128>,
                         cudaFuncAttributeMaxDynamicSharedMemorySize, ATTN_SMEM_128);

    pack_adj_kernel<<<NN, 1024>>>(adj, adjbits);

    // ----- layer 1 -----
    gemm_tf32x3_kernel<<<dim3(512/64, NN/64), 256>>>(x, W1, nullptr, h1, NN, 512, 512);
    esed_kernel<<<NN, 128>>>(h1, a1s, a1d, es, ed, 128);
    headmax_kernel<<<HH, 256>>>(ed, Mh);
    prep_kernel<<<(HH*NN)/256, 256>>>(es, ed, Mh, A1, A2, E1, E2);
    attn_tc3_kernel<128><<<dim3(NN/64, HH), 256, ATTN_SMEM_128>>>(
        h1, adjbits, es, ed, A1, A2, E1, E2, x1);

    gemm_tf32x3_kernel<<<dim3(1, NN/64), 256>>>(x1, lw1, lb1, t1, NN, 64, 512);
    bnelu_kernel<<<64, 256>>>(t1, g1, be1, x2, 64);

    // ----- layer 2 -----
    gemm_tf32x3_kernel<<<dim3(2, NN/64), 256>>>(x2, W2, nullptr, h2, NN, 128, 64);
    esed_kernel<<<NN, 128>>>(h2, a2s, a2d, es, ed, 32);
    headmax_kernel<<<HH, 256>>>(ed, Mh);
    prep_kernel<<<(HH*NN)/256, 256>>>(es, ed, Mh, A1, A2, E1, E2);
    attn_tc3_kernel<32><<<dim3(NN/64, HH), 256, ATTN_SMEM_32>>>(
        h2, adjbits, es, ed, A1, A2, E1, E2, x3);

    gemm_kernel<<<dim3(1, NN/64), 256>>>(x3, lw2, lb2, t2, NN, 16, 128);
    bnelu_kernel<<<16, 256>>>(t2, g2, be2, outp, 16);
}

// round 10
// speedup vs baseline: 1.2439x; 1.0009x over previous
#include <cuda_runtime.h>
#include <cuda_bf16.h>
#include <math.h>
#include <stdint.h>

#define NN   4096
#define HH   4
#define NW   (NN/32)     // 128 words per adjacency row

// ---------------- device scratch ----------------
__device__ uint32_t g_adjbits[NN * NW];          // 2 MB packed adjacency
__device__ float    g_h1 [NN * 512];             // x @ W1
__device__ float    g_x1 [NN * 512];             // GAT1 out
__device__ float    g_t1 [NN * 64];              // x1 @ lw1 + b
__device__ float    g_x2 [NN * 64];              // bn_elu
__device__ float    g_h2 [NN * 128];             // x2 @ W2
__device__ float    g_x3 [NN * 128];             // GAT2 out
__device__ float    g_t2 [NN * 16];              // x3 @ lw2 + b
__device__ float    g_es [HH * NN];
__device__ float    g_ed [HH * NN];
__device__ float    g_A1 [HH * NN];
__device__ float    g_A2 [HH * NN];
__device__ float    g_E1 [HH * NN];
__device__ float    g_E2 [HH * NN];

// ---------------- small helpers ----------------
__device__ __forceinline__ uint32_t f2tf(float x) {
    uint32_t r;
    asm("cvt.rna.tf32.f32 %0, %1;" : "=r"(r) : "f"(x));
    return r;
}

// 3xTF32 split: x ~= hi + lo, both tf32-representable
__device__ __forceinline__ void split_tf32(float x, uint32_t& hi, uint32_t& lo) {
    hi = f2tf(x);
    float r = x - __uint_as_float(hi);
    lo = f2tf(r);
}

__device__ __forceinline__ void mma_tf32(float c[4],
    const uint32_t a[4], uint32_t b0, uint32_t b1)
{
    asm volatile(
        "mma.sync.aligned.m16n8k8.row.col.f32.tf32.tf32.f32 "
        "{%0,%1,%2,%3}, {%4,%5,%6,%7}, {%8,%9}, {%0,%1,%2,%3};"
        : "+f"(c[0]), "+f"(c[1]), "+f"(c[2]), "+f"(c[3])
        : "r"(a[0]), "r"(a[1]), "r"(a[2]), "r"(a[3]), "r"(b0), "r"(b1));
}

// ---------------- pack adjacency to bitmask ----------------
__global__ void pack_adj_kernel(const int* __restrict__ adj, uint32_t* __restrict__ bits) {
    int row  = blockIdx.x;
    int warp = threadIdx.x >> 5;
    int lane = threadIdx.x & 31;
    for (int w = warp; w < NW; w += 32) {
        int v = adj[(size_t)row * NN + w * 32 + lane];
        unsigned m = __ballot_sync(0xffffffffu, v > 0);
        if (lane == 0) bits[row * NW + w] = m;
    }
}

// ---------------- 3xTF32 tensor-core GEMM: C[M,Nc] = A[M,K] @ B[K,Nc] (+bias) ----------------
// BM=64, BN=64, BK=32, 256 threads (8 warps). Requires M%64==0, Nc%64==0, K%32==0.
__global__ void __launch_bounds__(256) gemm_tf32x3_kernel(
    const float* __restrict__ A, const float* __restrict__ B,
    const float* __restrict__ bias, float* __restrict__ C,
    int M, int Nc, int K)
{
    __shared__ uint32_t Ah[64 * 36], Al[64 * 36];
    __shared__ uint32_t Bh[32 * 72], Bl[32 * 72];

    const int tid  = threadIdx.x;
    const int lane = tid & 31, warp = tid >> 5;
    const int wm = warp & 1;
    const int wn = warp >> 1;
    const int m0 = blockIdx.y * 64, n0 = blockIdx.x * 64;

    float acc[2][2][4] = {};

    for (int k0 = 0; k0 < K; k0 += 32) {
        #pragma unroll
        for (int v = 0; v < 2; v++) {
            int idx = v * 256 + tid;     // 64 x 8 float4
            int m = idx >> 3, kv = idx & 7;
            float4 a = *(const float4*)&A[(size_t)(m0 + m) * K + k0 + kv * 4];
            uint4 uh, ul;
            split_tf32(a.x, uh.x, ul.x); split_tf32(a.y, uh.y, ul.y);
            split_tf32(a.z, uh.z, ul.z); split_tf32(a.w, uh.w, ul.w);
            *(uint4*)&Ah[m * 36 + kv * 4] = uh;
            *(uint4*)&Al[m * 36 + kv * 4] = ul;
        }
        #pragma unroll
        for (int v = 0; v < 2; v++) {
            int idx = v * 256 + tid;     // 32 x 16 float4
            int k = idx >> 4, nv = idx & 15;
            float4 b = *(const float4*)&B[(size_t)(k0 + k) * Nc + n0 + nv * 4];
            uint4 uh, ul;
            split_tf32(b.x, uh.x, ul.x); split_tf32(b.y, uh.y, ul.y);
            split_tf32(b.z, uh.z, ul.z); split_tf32(b.w, uh.w, ul.w);
            *(uint4*)&Bh[k * 72 + nv * 4] = uh;
            *(uint4*)&Bl[k * 72 + nv * 4] = ul;
        }
        __syncthreads();

        #pragma unroll
        for (int ks = 0; ks < 4; ks++) {
            const int kk = ks * 8;
            uint32_t ah[2][4], al[2][4];
            #pragma unroll
            for (int mt = 0; mt < 2; mt++) {
                int r = 32 * wm + 16 * mt + (lane >> 2);
                int c = kk + (lane & 3);
                ah[mt][0] = Ah[r * 36 + c];       al[mt][0] = Al[r * 36 + c];
                ah[mt][1] = Ah[(r + 8) * 36 + c]; al[mt][1] = Al[(r + 8) * 36 + c];
                ah[mt][2] = Ah[r * 36 + c + 4];   al[mt][2] = Al[r * 36 + c + 4];
                ah[mt][3] = Ah[(r + 8) * 36 + c + 4]; al[mt][3] = Al[(r + 8) * 36 + c + 4];
            }
            #pragma unroll
            for (int nt = 0; nt < 2; nt++) {
                int col = 16 * wn + 8 * nt + (lane >> 2);
                int ro  = (kk + (lane & 3)) * 72 + col;
                uint32_t bh0 = Bh[ro], bh1 = Bh[ro + 4 * 72];
                uint32_t bl0 = Bl[ro], bl1 = Bl[ro + 4 * 72];
                #pragma unroll
                for (int mt = 0; mt < 2; mt++) {
                    mma_tf32(acc[mt][nt], ah[mt], bh0, bh1);
                    mma_tf32(acc[mt][nt], ah[mt], bl0, bl1);
                    mma_tf32(acc[mt][nt], al[mt], bh0, bh1);
                }
            }
        }
        __syncthreads();
    }

    #pragma unroll
    for (int mt = 0; mt < 2; mt++) {
        #pragma unroll
        for (int nt = 0; nt < 2; nt++) {
            int col = n0 + 16 * wn + 8 * nt + 2 * (lane & 3);
            float bx = bias ? bias[col]     : 0.f;
            float by = bias ? bias[col + 1] : 0.f;
            int r0 = m0 + 32 * wm + 16 * mt + (lane >> 2);
            float2 o0 = make_float2(acc[mt][nt][0] + bx, acc[mt][nt][1] + by);
            float2 o1 = make_float2(acc[mt][nt][2] + bx, acc[mt][nt][3] + by);
            *(float2*)&C[(size_t)r0 * Nc + col]       = o0;
            *(float2*)&C[(size_t)(r0 + 8) * Nc + col] = o1;
        }
    }
}

// ---------------- scalar GEMM (final Nc=16) ----------------
__global__ void __launch_bounds__(256) gemm_kernel(
    const float* __restrict__ A, const float* __restrict__ B,
    const float* __restrict__ bias, float* __restrict__ C,
    int M, int Nc, int K)
{
    __shared__ float As[16][68];
    __shared__ float Bs[16][68];
    int tx = threadIdx.x & 15, ty = threadIdx.x >> 4;
    int m0 = blockIdx.y * 64, n0 = blockIdx.x * 64;
    float acc[4][4] = {};

    for (int k0 = 0; k0 < K; k0 += 16) {
        {
            int m  = threadIdx.x >> 2;
            int kv = threadIdx.x & 3;
            float4 a = *(const float4*)&A[(size_t)(m0 + m) * K + k0 + kv * 4];
            As[kv*4+0][m] = a.x; As[kv*4+1][m] = a.y;
            As[kv*4+2][m] = a.z; As[kv*4+3][m] = a.w;
        }
        {
            int k  = threadIdx.x >> 4;
            int nv = threadIdx.x & 15;
            int n  = n0 + nv * 4;
            float4 b = make_float4(0.f, 0.f, 0.f, 0.f);
            if (n < Nc) b = *(const float4*)&B[(size_t)(k0 + k) * Nc + n];
            *(float4*)&Bs[k][nv*4] = b;
        }
        __syncthreads();
        #pragma unroll
        for (int k = 0; k < 16; k++) {
            float4 a4 = *(const float4*)&As[k][ty*4];
            float4 b4 = *(const float4*)&Bs[k][tx*4];
            float av[4] = {a4.x, a4.y, a4.z, a4.w};
            float bv[4] = {b4.x, b4.y, b4.z, b4.w};
            #pragma unroll
            for (int i = 0; i < 4; i++)
                #pragma unroll
                for (int j = 0; j < 4; j++)
                    acc[i][j] += av[i] * bv[j];
        }
        __syncthreads();
    }
    int col = n0 + tx * 4;
    if (col < Nc) {
        float4 bv = make_float4(0.f,0.f,0.f,0.f);
        if (bias) bv = *(const float4*)&bias[col];
        #pragma unroll
        for (int i = 0; i < 4; i++) {
            int row = m0 + ty * 4 + i;
            float4 o;
            o.x = acc[i][0] + bv.x; o.y = acc[i][1] + bv.y;
            o.z = acc[i][2] + bv.z; o.w = acc[i][3] + bv.w;
            *(float4*)&C[(size_t)row * Nc + col] = o;
        }
    }
}

// ---------------- es/ed + exp factors (fused; no max-shift needed: |es+ed| <~ 9) ----------------
__global__ void esed_prep_kernel(const float* __restrict__ h,
                                 const float* __restrict__ as_, const float* __restrict__ ad_,
                                 float* __restrict__ es, float* __restrict__ ed,
                                 float* __restrict__ A1, float* __restrict__ A2,
                                 float* __restrict__ E1, float* __restrict__ E2, int F)
{
    int i = blockIdx.x;
    int w = threadIdx.x >> 5, lane = threadIdx.x & 31;
    float s = 0.f, d = 0.f;
    for (int f = lane; f < F; f += 32) {
        float hv = h[(size_t)i * (HH * F) + w * F + f];
        s += hv * as_[w * F + f];
        d += hv * ad_[w * F + f];
    }
    #pragma unroll
    for (int off = 16; off; off >>= 1) {
        s += __shfl_xor_sync(0xffffffffu, s, off);
        d += __shfl_xor_sync(0xffffffffu, d, off);
    }
    if (lane == 0) {
        int idx = w * NN + i;
        es[idx] = s;  ed[idx] = d;
        A1[idx] = expf(s);        A2[idx] = expf(0.2f * s);
        E1[idx] = expf(d);        E2[idx] = expf(0.2f * d);
    }
}

// ---------------- 3xTF32 double-buffered fused masked-softmax attention ----------------
// out[i, head*F + f] = (1/Z_i) * sum_j w_ij * h[j, head*F + f]
// ONE __syncthreads per j-block; h-tile prefetched into registers while MMA runs.
template<int F>
__global__ void __launch_bounds__(256) attn_tc3_kernel(
    const float* __restrict__ hbuf,          // [N][H*F]
    const uint32_t* __restrict__ adjbits,    // [N][NW]
    const float* __restrict__ es, const float* __restrict__ ed,
    const float* __restrict__ A1g, const float* __restrict__ A2g,
    const float* __restrict__ E1g, const float* __restrict__ E2g,
    float* __restrict__ out)                 // [N][H*F]
{
    constexpr int TI  = 64;
    constexpr int JB  = 32;
    constexpr int LDH = HH * F;
    constexpr int HS  = F + 8;       // mod 32 == 8: conflict-free B-frag loads
    constexpr int WS  = 36;          // mod 32 == 4: conflict-free A-frag loads
    constexpr int NT  = F / 32;      // n-tiles per warp (4 for F=128, 1 for F=32)
    constexpr int NV  = JB * F / 1024;   // float4 per thread per h tile (4 or 1)
    constexpr int NB  = NN / JB;

    const int head = blockIdx.y;
    const int i0   = blockIdx.x * TI;
    const int tid  = threadIdx.x;
    const int lane = tid & 31, warp = tid >> 5;
    const int wm   = warp & 1;
    const int wn   = warp >> 1;

    extern __shared__ uint32_t smdyn[];
    uint32_t* h_hi = smdyn;                    // [2][JB*HS]
    uint32_t* h_lo = h_hi + 2 * JB * HS;       // [2][JB*HS]
    uint32_t* w_hi = h_lo + 2 * JB * HS;       // [2][TI*WS]
    uint32_t* w_lo = w_hi + 2 * TI * WS;       // [2][TI*WS]
    float* es_s = (float*)(w_lo + 2 * TI * WS);
    float* A1_s = es_s + TI;
    float* A2_s = A1_s + TI;
    float* z_s  = A2_s + TI;

    if (tid < TI) {
        es_s[tid] = es [head * NN + i0 + tid];
        A1_s[tid] = A1g[head * NN + i0 + tid];
        A2_s[tid] = A2g[head * NN + i0 + tid];
    }

    float acc[2][NT][4];
    #pragma unroll
    for (int mt = 0; mt < 2; mt++)
        #pragma unroll
        for (int nt = 0; nt < NT; nt++)
            #pragma unroll
            for (int q = 0; q < 4; q++) acc[mt][nt][q] = 0.f;

    float zpriv[8] = {0.f,0.f,0.f,0.f,0.f,0.f,0.f,0.f};
    const int r1base = warp * 8;

    // prefetch j-block 0
    float4 pre[NV];
    #pragma unroll
    for (int v = 0; v < NV; v++) {
        int idx = v * 256 + tid;
        int j   = idx / (F / 4);
        int f4  = idx % (F / 4);
        pre[v] = *(const float4*)&hbuf[(size_t)j * LDH + head * F + f4 * 4];
    }

    __syncthreads();   // es_s/A1_s/A2_s visible

    for (int jb = 0; jb < NB; jb++) {
        const int cur = jb & 1;
        uint32_t* hh = h_hi + cur * JB * HS;
        uint32_t* hl = h_lo + cur * JB * HS;
        uint32_t* wh = w_hi + cur * TI * WS;
        uint32_t* wl = w_lo + cur * TI * WS;

        // store prefetched h tile -> split tf32
        #pragma unroll
        for (int v = 0; v < NV; v++) {
            int idx = v * 256 + tid;
            int j   = idx / (F / 4);
            int f4  = idx % (F / 4);
            uint4 uh, ul;
            split_tf32(pre[v].x, uh.x, ul.x); split_tf32(pre[v].y, uh.y, ul.y);
            split_tf32(pre[v].z, uh.z, ul.z); split_tf32(pre[v].w, uh.w, ul.w);
            *(uint4*)&hh[j * HS + f4 * 4] = uh;
            *(uint4*)&hl[j * HS + f4 * 4] = ul;
        }
        // build w tile [TI][JB]; thread column j=lane, 8 rows per warp
        {
            int jg = jb * JB + lane;
            float edv = ed [head * NN + jg];
            float e1  = E1g[head * NN + jg];
            float e2  = E2g[head * NN + jg];
            #pragma unroll
            for (int k = 0; k < 8; k++) {
                int r = r1base + k;
                uint32_t word = adjbits[(size_t)(i0 + r) * NW + jb];
                float s = es_s[r] + edv;
                float w = (s >= 0.f) ? A1_s[r] * e1 : A2_s[r] * e2;
                w = ((word >> lane) & 1u) ? w : 0.f;
                zpriv[k] += w;
                uint32_t whi, wlo;
                split_tf32(w, whi, wlo);
                wh[r * WS + lane] = whi;
                wl[r * WS + lane] = wlo;
            }
        }
        __syncthreads();   // the single barrier: tiles[cur] complete, tiles[cur^1] free

        // prefetch next j-block (latency hidden behind MMA below)
        if (jb + 1 < NB) {
            #pragma unroll
            for (int v = 0; v < NV; v++) {
                int idx = v * 256 + tid;
                int j   = (jb + 1) * JB + idx / (F / 4);
                int f4  = idx % (F / 4);
                pre[v] = *(const float4*)&hbuf[(size_t)j * LDH + head * F + f4 * 4];
            }
        }

        // C += w @ h via 3xTF32 mma
        #pragma unroll
        for (int ks = 0; ks < 4; ks++) {
            const int kk = ks * 8;
            uint32_t ah[2][4], al[2][4];
            #pragma unroll
            for (int mt = 0; mt < 2; mt++) {
                int r = 32 * wm + 16 * mt + (lane >> 2);
                int c = kk + (lane & 3);
                ah[mt][0] = wh[r * WS + c];       al[mt][0] = wl[r * WS + c];
                ah[mt][1] = wh[(r + 8) * WS + c]; al[mt][1] = wl[(r + 8) * WS + c];
                ah[mt][2] = wh[r * WS + c + 4];   al[mt][2] = wl[r * WS + c + 4];
                ah[mt][3] = wh[(r + 8) * WS + c + 4]; al[mt][3] = wl[(r + 8) * WS + c + 4];
            }
            #pragma unroll
            for (int nt = 0; nt < NT; nt++) {
                int col = wn * 8 * NT + 8 * nt + (lane >> 2);
                int ro  = (kk + (lane & 3)) * HS + col;
                uint32_t bh0 = hh[ro], bh1 = hh[ro + 4 * HS];
                uint32_t bl0 = hl[ro], bl1 = hl[ro + 4 * HS];
                #pragma unroll
                for (int mt = 0; mt < 2; mt++) {
                    mma_tf32(acc[mt][nt], ah[mt], bh0, bh1);
                    mma_tf32(acc[mt][nt], ah[mt], bl0, bl1);
                    mma_tf32(acc[mt][nt], al[mt], bh0, bh1);
                }
            }
        }
    }

    // Z reduction: each warp's lanes hold partial sums over j for its 8 rows
    #pragma unroll
    for (int k = 0; k < 8; k++) {
        float z = zpriv[k];
        #pragma unroll
        for (int off = 16; off; off >>= 1) z += __shfl_xor_sync(0xffffffffu, z, off);
        if (lane == 0) z_s[r1base + k] = z;
    }
    __syncthreads();

    // epilogue: divide by Z, store
    #pragma unroll
    for (int mt = 0; mt < 2; mt++) {
        int r0 = 32 * wm + 16 * mt + (lane >> 2);
        int r1 = r0 + 8;
        float zi0 = 1.f / z_s[r0];
        float zi1 = 1.f / z_s[r1];
        #pragma unroll
        for (int nt = 0; nt < NT; nt++) {
            int col = wn * 8 * NT + 8 * nt + 2 * (lane & 3);
            float2 o0 = make_float2(acc[mt][nt][0] * zi0, acc[mt][nt][1] * zi0);
            float2 o1 = make_float2(acc[mt][nt][2] * zi1, acc[mt][nt][3] * zi1);
            *(float2*)&out[(size_t)(i0 + r0) * LDH + head * F + col] = o0;
            *(float2*)&out[(size_t)(i0 + r1) * LDH + head * F + col] = o1;
        }
    }
}

// ---------------- BatchNorm (over rows) + ELU ----------------
__global__ void bnelu_kernel(const float* __restrict__ X,
                             const float* __restrict__ gamma, const float* __restrict__ beta,
                             float* __restrict__ Y, int C)
{
    int c = blockIdx.x;
    int t = threadIdx.x;
    float v[16];
    float s = 0.f, sq = 0.f;
    #pragma unroll
    for (int k = 0; k < 16; k++) {
        float x = X[(size_t)(t + k * 256) * C + c];
        v[k] = x; s += x; sq += x * x;
    }
    __shared__ float rs[256], rq[256];
    rs[t] = s; rq[t] = sq; __syncthreads();
    for (int o = 128; o; o >>= 1) {
        if (t < o) { rs[t] += rs[t + o]; rq[t] += rq[t + o]; }
        __syncthreads();
    }
    float mean = rs[0] * (1.f / NN);
    float var  = rq[0] * (1.f / NN) - mean * mean;
    float scale = rsqrtf(var + 1e-5f);
    float gm = gamma[c], bt = beta[c];
    #pragma unroll
    for (int k = 0; k < 16; k++) {
        float y = (v[k] - mean) * scale * gm + bt;
        y = (y > 0.f) ? y : expm1f(y);
        Y[(size_t)(t + k * 256) * C + c] = y;
    }
}

// ---------------- host ----------------
static inline void* sym(const void* s) { void* p = nullptr; cudaGetSymbolAddress(&p, s); return p; }

// dynamic smem sizes for attn kernels (double-buffered)
static constexpr int ATTN_SMEM_128 = (2*2*32*(128+8) + 2*2*64*36 + 4*64) * 4; // 107520 B
static constexpr int ATTN_SMEM_32  = (2*2*32*(32+8)  + 2*2*64*36 + 4*64) * 4; // 58368 B

extern "C" void kernel_launch(void* const* d_in, const int* in_sizes, int n_in,
                              void* d_out, int out_size)
{
    const float* x   = (const float*)d_in[0];
    const int*   adj = (const int*)  d_in[1];
    const float* W1  = (const float*)d_in[2];
    const float* a1s = (const float*)d_in[3];
    const float* a1d = (const float*)d_in[4];
    const float* lw1 = (const float*)d_in[5];
    const float* lb1 = (const float*)d_in[6];
    const float* g1  = (const float*)d_in[7];
    const float* be1 = (const float*)d_in[8];
    const float* W2  = (const float*)d_in[9];
    const float* a2s = (const float*)d_in[10];
    const float* a2d = (const float*)d_in[11];
    const float* lw2 = (const float*)d_in[12];
    const float* lb2 = (const float*)d_in[13];
    const float* g2  = (const float*)d_in[14];
    const float* be2 = (const float*)d_in[15];
    float* outp = (float*)d_out;

    uint32_t* adjbits = (uint32_t*)sym(g_adjbits);
    float* h1 = (float*)sym(g_h1);
    float* x1 = (float*)sym(g_x1);
    float* t1 = (float*)sym(g_t1);
    float* x2 = (float*)sym(g_x2);
    float* h2 = (float*)sym(g_h2);
    float* x3 = (float*)sym(g_x3);
    float* t2 = (float*)sym(g_t2);
    float* es = (float*)sym(g_es);
    float* ed = (float*)sym(g_ed);
    float* A1 = (float*)sym(g_A1);
    float* A2 = (float*)sym(g_A2);
    float* E1 = (float*)sym(g_E1);
    float* E2 = (float*)sym(g_E2);

    // opt-in >48KB dynamic smem (idempotent, capture-safe)
    cudaFuncSetAttribute(attn_tc3_kernel<128>,
                         cudaFuncAttributeMaxDynamicSharedMemorySize, ATTN_SMEM_128);
    cudaFuncSetAttribute(attn_tc3_kernel<32>,
                         cudaFuncAttributeMaxDynamicSharedMemorySize, ATTN_SMEM_32);

    pack_adj_kernel<<<NN, 1024>>>(adj, adjbits);

    // ----- layer 1 -----
    gemm_tf32x3_kernel<<<dim3(512/64, NN/64), 256>>>(x, W1, nullptr, h1, NN, 512, 512);
    esed_prep_kernel<<<NN, 128>>>(h1, a1s, a1d, es, ed, A1, A2, E1, E2, 128);
    attn_tc3_kernel<128><<<dim3(NN/64, HH), 256, ATTN_SMEM_128>>>(
        h1, adjbits, es, ed, A1, A2, E1, E2, x1);

    gemm_tf32x3_kernel<<<dim3(1, NN/64), 256>>>(x1, lw1, lb1, t1, NN, 64, 512);
    bnelu_kernel<<<64, 256>>>(t1, g1, be1, x2, 64);

    // ----- layer 2 -----
    gemm_tf32x3_kernel<<<dim3(2, NN/64), 256>>>(x2, W2, nullptr, h2, NN, 128, 64);
    esed_prep_kernel<<<NN, 128>>>(h2, a2s, a2d, es, ed, A1, A2, E1, E2, 32);
    attn_tc3_kernel<32><<<dim3(NN/64, HH), 256, ATTN_SMEM_32>>>(
        h2, adjbits, es, ed, A1, A2, E1, E2, x3);

    gemm_kernel<<<dim3(1, NN/64), 256>>>(x3, lw2, lb2, t2, NN, 16, 128);
    bnelu_kernel<<<16, 256>>>(t2, g2, be2, outp, 16);
}

// round 13
// speedup vs baseline: 1.4447x; 1.1615x over previous
#include <cuda_runtime.h>
#include <cuda_bf16.h>
#include <math.h>
#include <stdint.h>

#define NN   4096
#define HH   4
#define NW   (NN/32)     // 128 words per adjacency row

// ---------------- device scratch ----------------
__device__ uint32_t g_adjbits[NN * NW];          // 2 MB packed adjacency
__device__ float    g_h1 [NN * 512];             // x @ W1
__device__ float    g_x1 [NN * 512];             // GAT1 out
__device__ float    g_t1 [NN * 64];              // x1 @ lw1 + b
__device__ float    g_x2 [NN * 64];              // bn_elu
__device__ float    g_h2 [NN * 128];             // x2 @ W2
__device__ float    g_x3 [NN * 128];             // GAT2 out
__device__ float    g_t2 [NN * 16];              // x3 @ lw2 + b
__device__ float    g_es [HH * NN];
__device__ float    g_ed [HH * NN];
__device__ float    g_A1 [HH * NN];
__device__ float    g_A2 [HH * NN];
__device__ float    g_E1 [HH * NN];
__device__ float    g_E2 [HH * NN];

// ---------------- small helpers ----------------
__device__ __forceinline__ uint32_t f2tf(float x) {
    uint32_t r;
    asm("cvt.rna.tf32.f32 %0, %1;" : "=r"(r) : "f"(x));
    return r;
}

// 3xTF32 split: x ~= hi + lo, both tf32-representable
__device__ __forceinline__ void split_tf32(float x, uint32_t& hi, uint32_t& lo) {
    hi = f2tf(x);
    float r = x - __uint_as_float(hi);
    lo = f2tf(r);
}

__device__ __forceinline__ void mma_tf32(float c[4],
    const uint32_t a[4], uint32_t b0, uint32_t b1)
{
    asm volatile(
        "mma.sync.aligned.m16n8k8.row.col.f32.tf32.tf32.f32 "
        "{%0,%1,%2,%3}, {%4,%5,%6,%7}, {%8,%9}, {%0,%1,%2,%3};"
        : "+f"(c[0]), "+f"(c[1]), "+f"(c[2]), "+f"(c[3])
        : "r"(a[0]), "r"(a[1]), "r"(a[2]), "r"(a[3]), "r"(b0), "r"(b1));
}

// ---------------- pack adjacency to bitmask ----------------
__global__ void pack_adj_kernel(const int* __restrict__ adj, uint32_t* __restrict__ bits) {
    int row  = blockIdx.x;
    int warp = threadIdx.x >> 5;
    int lane = threadIdx.x & 31;
    for (int w = warp; w < NW; w += 32) {
        int v = adj[(size_t)row * NN + w * 32 + lane];
        unsigned m = __ballot_sync(0xffffffffu, v > 0);
        if (lane == 0) bits[row * NW + w] = m;
    }
}

// ---------------- 3xTF32 tensor-core GEMM: C[M,Nc] = A[M,K] @ B[K,Nc] (+bias) ----------------
// BM=64, BN=64, BK=32, 256 threads (8 warps). Requires M%64==0, Nc%64==0, K%32==0.
__global__ void __launch_bounds__(256) gemm_tf32x3_kernel(
    const float* __restrict__ A, const float* __restrict__ B,
    const float* __restrict__ bias, float* __restrict__ C,
    int M, int Nc, int K)
{
    __shared__ uint32_t Ah[64 * 36], Al[64 * 36];
    __shared__ uint32_t Bh[32 * 72], Bl[32 * 72];

    const int tid  = threadIdx.x;
    const int lane = tid & 31, warp = tid >> 5;
    const int wm = warp & 1;
    const int wn = warp >> 1;
    const int m0 = blockIdx.y * 64, n0 = blockIdx.x * 64;

    float acc[2][2][4] = {};

    for (int k0 = 0; k0 < K; k0 += 32) {
        #pragma unroll
        for (int v = 0; v < 2; v++) {
            int idx = v * 256 + tid;     // 64 x 8 float4
            int m = idx >> 3, kv = idx & 7;
            float4 a = *(const float4*)&A[(size_t)(m0 + m) * K + k0 + kv * 4];
            uint4 uh, ul;
            split_tf32(a.x, uh.x, ul.x); split_tf32(a.y, uh.y, ul.y);
            split_tf32(a.z, uh.z, ul.z); split_tf32(a.w, uh.w, ul.w);
            *(uint4*)&Ah[m * 36 + kv * 4] = uh;
            *(uint4*)&Al[m * 36 + kv * 4] = ul;
        }
        #pragma unroll
        for (int v = 0; v < 2; v++) {
            int idx = v * 256 + tid;     // 32 x 16 float4
            int k = idx >> 4, nv = idx & 15;
            float4 b = *(const float4*)&B[(size_t)(k0 + k) * Nc + n0 + nv * 4];
            uint4 uh, ul;
            split_tf32(b.x, uh.x, ul.x); split_tf32(b.y, uh.y, ul.y);
            split_tf32(b.z, uh.z, ul.z); split_tf32(b.w, uh.w, ul.w);
            *(uint4*)&Bh[k * 72 + nv * 4] = uh;
            *(uint4*)&Bl[k * 72 + nv * 4] = ul;
        }
        __syncthreads();

        #pragma unroll
        for (int ks = 0; ks < 4; ks++) {
            const int kk = ks * 8;
            uint32_t ah[2][4], al[2][4];
            #pragma unroll
            for (int mt = 0; mt < 2; mt++) {
                int r = 32 * wm + 16 * mt + (lane >> 2);
                int c = kk + (lane & 3);
                ah[mt][0] = Ah[r * 36 + c];       al[mt][0] = Al[r * 36 + c];
                ah[mt][1] = Ah[(r + 8) * 36 + c]; al[mt][1] = Al[(r + 8) * 36 + c];
                ah[mt][2] = Ah[r * 36 + c + 4];   al[mt][2] = Al[r * 36 + c + 4];
                ah[mt][3] = Ah[(r + 8) * 36 + c + 4]; al[mt][3] = Al[(r + 8) * 36 + c + 4];
            }
            #pragma unroll
            for (int nt = 0; nt < 2; nt++) {
                int col = 16 * wn + 8 * nt + (lane >> 2);
                int ro  = (kk + (lane & 3)) * 72 + col;
                uint32_t bh0 = Bh[ro], bh1 = Bh[ro + 4 * 72];
                uint32_t bl0 = Bl[ro], bl1 = Bl[ro + 4 * 72];
                #pragma unroll
                for (int mt = 0; mt < 2; mt++) {
                    mma_tf32(acc[mt][nt], ah[mt], bh0, bh1);
                    mma_tf32(acc[mt][nt], ah[mt], bl0, bl1);
                    mma_tf32(acc[mt][nt], al[mt], bh0, bh1);
                }
            }
        }
        __syncthreads();
    }

    #pragma unroll
    for (int mt = 0; mt < 2; mt++) {
        #pragma unroll
        for (int nt = 0; nt < 2; nt++) {
            int col = n0 + 16 * wn + 8 * nt + 2 * (lane & 3);
            float bx = bias ? bias[col]     : 0.f;
            float by = bias ? bias[col + 1] : 0.f;
            int r0 = m0 + 32 * wm + 16 * mt + (lane >> 2);
            float2 o0 = make_float2(acc[mt][nt][0] + bx, acc[mt][nt][1] + by);
            float2 o1 = make_float2(acc[mt][nt][2] + bx, acc[mt][nt][3] + by);
            *(float2*)&C[(size_t)r0 * Nc + col]       = o0;
            *(float2*)&C[(size_t)(r0 + 8) * Nc + col] = o1;
        }
    }
}

// ---------------- scalar GEMM (final Nc=16) ----------------
__global__ void __launch_bounds__(256) gemm_kernel(
    const float* __restrict__ A, const float* __restrict__ B,
    const float* __restrict__ bias, float* __restrict__ C,
    int M, int Nc, int K)
{
    __shared__ float As[16][68];
    __shared__ float Bs[16][68];
    int tx = threadIdx.x & 15, ty = threadIdx.x >> 4;
    int m0 = blockIdx.y * 64, n0 = blockIdx.x * 64;
    float acc[4][4] = {};

    for (int k0 = 0; k0 < K; k0 += 16) {
        {
            int m  = threadIdx.x >> 2;
            int kv = threadIdx.x & 3;
            float4 a = *(const float4*)&A[(size_t)(m0 + m) * K + k0 + kv * 4];
            As[kv*4+0][m] = a.x; As[kv*4+1][m] = a.y;
            As[kv*4+2][m] = a.z; As[kv*4+3][m] = a.w;
        }
        {
            int k  = threadIdx.x >> 4;
            int nv = threadIdx.x & 15;
            int n  = n0 + nv * 4;
            float4 b = make_float4(0.f, 0.f, 0.f, 0.f);
            if (n < Nc) b = *(const float4*)&B[(size_t)(k0 + k) * Nc + n];
            *(float4*)&Bs[k][nv*4] = b;
        }
        __syncthreads();
        #pragma unroll
        for (int k = 0; k < 16; k++) {
            float4 a4 = *(const float4*)&As[k][ty*4];
            float4 b4 = *(const float4*)&Bs[k][tx*4];
            float av[4] = {a4.x, a4.y, a4.z, a4.w};
            float bv[4] = {b4.x, b4.y, b4.z, b4.w};
            #pragma unroll
            for (int i = 0; i < 4; i++)
                #pragma unroll
                for (int j = 0; j < 4; j++)
                    acc[i][j] += av[i] * bv[j];
        }
        __syncthreads();
    }
    int col = n0 + tx * 4;
    if (col < Nc) {
        float4 bv = make_float4(0.f,0.f,0.f,0.f);
        if (bias) bv = *(const float4*)&bias[col];
        #pragma unroll
        for (int i = 0; i < 4; i++) {
            int row = m0 + ty * 4 + i;
            float4 o;
            o.x = acc[i][0] + bv.x; o.y = acc[i][1] + bv.y;
            o.z = acc[i][2] + bv.z; o.w = acc[i][3] + bv.w;
            *(float4*)&C[(size_t)row * Nc + col] = o;
        }
    }
}

// ---------------- es/ed + exp factors (fused; no max-shift needed: |es+ed| <~ 9) ----------------
__global__ void esed_prep_kernel(const float* __restrict__ h,
                                 const float* __restrict__ as_, const float* __restrict__ ad_,
                                 float* __restrict__ es, float* __restrict__ ed,
                                 float* __restrict__ A1, float* __restrict__ A2,
                                 float* __restrict__ E1, float* __restrict__ E2, int F)
{
    int i = blockIdx.x;
    int w = threadIdx.x >> 5, lane = threadIdx.x & 31;
    float s = 0.f, d = 0.f;
    for (int f = lane; f < F; f += 32) {
        float hv = h[(size_t)i * (HH * F) + w * F + f];
        s += hv * as_[w * F + f];
        d += hv * ad_[w * F + f];
    }
    #pragma unroll
    for (int off = 16; off; off >>= 1) {
        s += __shfl_xor_sync(0xffffffffu, s, off);
        d += __shfl_xor_sync(0xffffffffu, d, off);
    }
    if (lane == 0) {
        int idx = w * NN + i;
        es[idx] = s;  ed[idx] = d;
        A1[idx] = expf(s);        A2[idx] = expf(0.2f * s);
        E1[idx] = expf(d);        E2[idx] = expf(0.2f * d);
    }
}

// ---------------- 2xTF32 double-buffered fused masked-softmax attention ----------------
// out[i, head*F + f] = (1/Z_i) * sum_j w_ij * h[j, head*F + f]
// w is split (exact); h carries one tf32 rounding -> 2 MMAs per k-step.
template<int F>
__global__ void __launch_bounds__(256) attn_tc3_kernel(
    const float* __restrict__ hbuf,          // [N][H*F]
    const uint32_t* __restrict__ adjbits,    // [N][NW]
    const float* __restrict__ es, const float* __restrict__ ed,
    const float* __restrict__ A1g, const float* __restrict__ A2g,
    const float* __restrict__ E1g, const float* __restrict__ E2g,
    float* __restrict__ out)                 // [N][H*F]
{
    constexpr int TI  = 64;
    constexpr int JB  = 32;
    constexpr int LDH = HH * F;
    constexpr int HS  = F + 8;       // mod 32 == 8: conflict-free B-frag loads
    constexpr int WS  = 36;          // mod 32 == 4: conflict-free A-frag loads
    constexpr int NT  = F / 32;      // n-tiles per warp (4 for F=128, 1 for F=32)
    constexpr int NV  = JB * F / 1024;   // float4 per thread per h tile (4 or 1)
    constexpr int NB  = NN / JB;

    const int head = blockIdx.y;
    const int i0   = blockIdx.x * TI;
    const int tid  = threadIdx.x;
    const int lane = tid & 31, warp = tid >> 5;
    const int wm   = warp & 1;
    const int wn   = warp >> 1;

    extern __shared__ uint32_t smdyn[];
    uint32_t* h_hi = smdyn;                    // [2][JB*HS]
    uint32_t* w_hi = h_hi + 2 * JB * HS;       // [2][TI*WS]
    uint32_t* w_lo = w_hi + 2 * TI * WS;       // [2][TI*WS]
    float* es_s = (float*)(w_lo + 2 * TI * WS);
    float* A1_s = es_s + TI;
    float* A2_s = A1_s + TI;
    float* z_s  = A2_s + TI;

    if (tid < TI) {
        es_s[tid] = es [head * NN + i0 + tid];
        A1_s[tid] = A1g[head * NN + i0 + tid];
        A2_s[tid] = A2g[head * NN + i0 + tid];
    }

    float acc[2][NT][4];
    #pragma unroll
    for (int mt = 0; mt < 2; mt++)
        #pragma unroll
        for (int nt = 0; nt < NT; nt++)
            #pragma unroll
            for (int q = 0; q < 4; q++) acc[mt][nt][q] = 0.f;

    float zpriv[8] = {0.f,0.f,0.f,0.f,0.f,0.f,0.f,0.f};
    const int r1base = warp * 8;

    // prefetch j-block 0
    float4 pre[NV];
    #pragma unroll
    for (int v = 0; v < NV; v++) {
        int idx = v * 256 + tid;
        int j   = idx / (F / 4);
        int f4  = idx % (F / 4);
        pre[v] = *(const float4*)&hbuf[(size_t)j * LDH + head * F + f4 * 4];
    }

    __syncthreads();   // es_s/A1_s/A2_s visible

    for (int jb = 0; jb < NB; jb++) {
        const int cur = jb & 1;
        uint32_t* hh = h_hi + cur * JB * HS;
        uint32_t* wh = w_hi + cur * TI * WS;
        uint32_t* wl = w_lo + cur * TI * WS;

        // store prefetched h tile -> tf32 (single rounding; no lo tile)
        #pragma unroll
        for (int v = 0; v < NV; v++) {
            int idx = v * 256 + tid;
            int j   = idx / (F / 4);
            int f4  = idx % (F / 4);
            uint4 uh = make_uint4(f2tf(pre[v].x), f2tf(pre[v].y),
                                  f2tf(pre[v].z), f2tf(pre[v].w));
            *(uint4*)&hh[j * HS + f4 * 4] = uh;
        }
        // build w tile [TI][JB]; thread column j=lane, 8 rows per warp
        {
            int jg = jb * JB + lane;
            float edv = ed [head * NN + jg];
            float e1  = E1g[head * NN + jg];
            float e2  = E2g[head * NN + jg];
            #pragma unroll
            for (int k = 0; k < 8; k++) {
                int r = r1base + k;
                uint32_t word = adjbits[(size_t)(i0 + r) * NW + jb];
                float s = es_s[r] + edv;
                float w = (s >= 0.f) ? A1_s[r] * e1 : A2_s[r] * e2;
                w = ((word >> lane) & 1u) ? w : 0.f;
                zpriv[k] += w;
                uint32_t whi, wlo;
                split_tf32(w, whi, wlo);
                wh[r * WS + lane] = whi;
                wl[r * WS + lane] = wlo;
            }
        }
        __syncthreads();   // the single barrier: tiles[cur] complete, tiles[cur^1] free

        // prefetch next j-block (latency hidden behind MMA below)
        if (jb + 1 < NB) {
            #pragma unroll
            for (int v = 0; v < NV; v++) {
                int idx = v * 256 + tid;
                int j   = (jb + 1) * JB + idx / (F / 4);
                int f4  = idx % (F / 4);
                pre[v] = *(const float4*)&hbuf[(size_t)j * LDH + head * F + f4 * 4];
            }
        }

        // C += (w_hi + w_lo) @ h_tf32 via 2 MMAs per k-step
        #pragma unroll
        for (int ks = 0; ks < 4; ks++) {
            const int kk = ks * 8;
            uint32_t ah[2][4], al[2][4];
            #pragma unroll
            for (int mt = 0; mt < 2; mt++) {
                int r = 32 * wm + 16 * mt + (lane >> 2);
                int c = kk + (lane & 3);
                ah[mt][0] = wh[r * WS + c];       al[mt][0] = wl[r * WS + c];
                ah[mt][1] = wh[(r + 8) * WS + c]; al[mt][1] = wl[(r + 8) * WS + c];
                ah[mt][2] = wh[r * WS + c + 4];   al[mt][2] = wl[r * WS + c + 4];
                ah[mt][3] = wh[(r + 8) * WS + c + 4]; al[mt][3] = wl[(r + 8) * WS + c + 4];
            }
            #pragma unroll
            for (int nt = 0; nt < NT; nt++) {
                int col = wn * 8 * NT + 8 * nt + (lane >> 2);
                int ro  = (kk + (lane & 3)) * HS + col;
                uint32_t bh0 = hh[ro], bh1 = hh[ro + 4 * HS];
                #pragma unroll
                for (int mt = 0; mt < 2; mt++) {
                    mma_tf32(acc[mt][nt], ah[mt], bh0, bh1);
                    mma_tf32(acc[mt][nt], al[mt], bh0, bh1);
                }
            }
        }
    }

    // Z reduction: each warp's lanes hold partial sums over j for its 8 rows
    #pragma unroll
    for (int k = 0; k < 8; k++) {
        float z = zpriv[k];
        #pragma unroll
        for (int off = 16; off; off >>= 1) z += __shfl_xor_sync(0xffffffffu, z, off);
        if (lane == 0) z_s[r1base + k] = z;
    }
    __syncthreads();

    // epilogue: divide by Z, store
    #pragma unroll
    for (int mt = 0; mt < 2; mt++) {
        int r0 = 32 * wm + 16 * mt + (lane >> 2);
        int r1 = r0 + 8;
        float zi0 = 1.f / z_s[r0];
        float zi1 = 1.f / z_s[r1];
        #pragma unroll
        for (int nt = 0; nt < NT; nt++) {
            int col = wn * 8 * NT + 8 * nt + 2 * (lane & 3);
            float2 o0 = make_float2(acc[mt][nt][0] * zi0, acc[mt][nt][1] * zi0);
            float2 o1 = make_float2(acc[mt][nt][2] * zi1, acc[mt][nt][3] * zi1);
            *(float2*)&out[(size_t)(i0 + r0) * LDH + head * F + col] = o0;
            *(float2*)&out[(size_t)(i0 + r1) * LDH + head * F + col] = o1;
        }
    }
}

// ---------------- BatchNorm (over rows) + ELU ----------------
__global__ void bnelu_kernel(const float* __restrict__ X,
                             const float* __restrict__ gamma, const float* __restrict__ beta,
                             float* __restrict__ Y, int C)
{
    int c = blockIdx.x;
    int t = threadIdx.x;
    float v[16];
    float s = 0.f, sq = 0.f;
    #pragma unroll
    for (int k = 0; k < 16; k++) {
        float x = X[(size_t)(t + k * 256) * C + c];
        v[k] = x; s += x; sq += x * x;
    }
    __shared__ float rs[256], rq[256];
    rs[t] = s; rq[t] = sq; __syncthreads();
    for (int o = 128; o; o >>= 1) {
        if (t < o) { rs[t] += rs[t + o]; rq[t] += rq[t + o]; }
        __syncthreads();
    }
    float mean = rs[0] * (1.f / NN);
    float var  = rq[0] * (1.f / NN) - mean * mean;
    float scale = rsqrtf(var + 1e-5f);
    float gm = gamma[c], bt = beta[c];
    #pragma unroll
    for (int k = 0; k < 16; k++) {
        float y = (v[k] - mean) * scale * gm + bt;
        y = (y > 0.f) ? y : expm1f(y);
        Y[(size_t)(t + k * 256) * C + c] = y;
    }
}

// ---------------- host ----------------
static inline void* sym(const void* s) { void* p = nullptr; cudaGetSymbolAddress(&p, s); return p; }

// dynamic smem sizes for attn kernels (double-buffered, h hi-only)
static constexpr int ATTN_SMEM_128 = (2*32*(128+8) + 2*2*64*36 + 4*64) * 4; // 72704 B
static constexpr int ATTN_SMEM_32  = (2*32*(32+8)  + 2*2*64*36 + 4*64) * 4; // 48128 B

extern "C" void kernel_launch(void* const* d_in, const int* in_sizes, int n_in,
                              void* d_out, int out_size)
{
    const float* x   = (const float*)d_in[0];
    const int*   adj = (const int*)  d_in[1];
    const float* W1  = (const float*)d_in[2];
    const float* a1s = (const float*)d_in[3];
    const float* a1d = (const float*)d_in[4];
    const float* lw1 = (const float*)d_in[5];
    const float* lb1 = (const float*)d_in[6];
    const float* g1  = (const float*)d_in[7];
    const float* be1 = (const float*)d_in[8];
    const float* W2  = (const float*)d_in[9];
    const float* a2s = (const float*)d_in[10];
    const float* a2d = (const float*)d_in[11];
    const float* lw2 = (const float*)d_in[12];
    const float* lb2 = (const float*)d_in[13];
    const float* g2  = (const float*)d_in[14];
    const float* be2 = (const float*)d_in[15];
    float* outp = (float*)d_out;

    uint32_t* adjbits = (uint32_t*)sym(g_adjbits);
    float* h1 = (float*)sym(g_h1);
    float* x1 = (float*)sym(g_x1);
    float* t1 = (float*)sym(g_t1);
    float* x2 = (float*)sym(g_x2);
    float* h2 = (float*)sym(g_h2);
    float* x3 = (float*)sym(g_x3);
    float* t2 = (float*)sym(g_t2);
    float* es = (float*)sym(g_es);
    float* ed = (float*)sym(g_ed);
    float* A1 = (float*)sym(g_A1);
    float* A2 = (float*)sym(g_A2);
    float* E1 = (float*)sym(g_E1);
    float* E2 = (float*)sym(g_E2);

    // opt-in >48KB dynamic smem (idempotent, capture-safe)
    cudaFuncSetAttribute(attn_tc3_kernel<128>,
                         cudaFuncAttributeMaxDynamicSharedMemorySize, ATTN_SMEM_128);
    cudaFuncSetAttribute(attn_tc3_kernel<32>,
                         cudaFuncAttributeMaxDynamicSharedMemorySize, ATTN_SMEM_32);

    pack_adj_kernel<<<NN, 1024>>>(adj, adjbits);

    // ----- layer 1 -----
    gemm_tf32x3_kernel<<<dim3(512/64, NN/64), 256>>>(x, W1, nullptr, h1, NN, 512, 512);
    esed_prep_kernel<<<NN, 128>>>(h1, a1s, a1d, es, ed, A1, A2, E1, E2, 128);
    attn_tc3_kernel<128><<<dim3(NN/64, HH), 256, ATTN_SMEM_128>>>(
        h1, adjbits, es, ed, A1, A2, E1, E2, x1);

    gemm_tf32x3_kernel<<<dim3(1, NN/64), 256>>>(x1, lw1, lb1, t1, NN, 64, 512);
    bnelu_kernel<<<64, 256>>>(t1, g1, be1, x2, 64);

    // ----- layer 2 -----
    gemm_tf32x3_kernel<<<dim3(2, NN/64), 256>>>(x2, W2, nullptr, h2, NN, 128, 64);
    esed_prep_kernel<<<NN, 128>>>(h2, a2s, a2d, es, ed, A1, A2, E1, E2, 32);
    attn_tc3_kernel<32><<<dim3(NN/64, HH), 256, ATTN_SMEM_32>>>(
        h2, adjbits, es, ed, A1, A2, E1, E2, x3);

    gemm_kernel<<<dim3(1, NN/64), 256>>>(x3, lw2, lb2, t2, NN, 16, 128);
    bnelu_kernel<<<16, 256>>>(t2, g2, be2, outp, 16);
}

// round 14
// speedup vs baseline: 1.4996x; 1.0380x over previous
#include <cuda_runtime.h>
#include <cuda_bf16.h>
#include <math.h>
#include <stdint.h>

#define NN   4096
#define HH   4
#define NW   (NN/32)     // 128 words per adjacency row

// ---------------- device scratch ----------------
__device__ uint32_t g_adjbits[NN * NW];          // 2 MB packed adjacency
__device__ float    g_h1 [NN * 512];             // x @ W1
__device__ float    g_x1 [NN * 512];             // GAT1 out
__device__ float    g_t1 [NN * 64];              // x1 @ lw1 + b
__device__ float    g_x2 [NN * 64];              // bn_elu
__device__ float    g_h2 [NN * 128];             // x2 @ W2
__device__ float    g_x3 [NN * 128];             // GAT2 out
__device__ float    g_t2 [NN * 16];              // x3 @ lw2 + b
__device__ float    g_es [HH * NN];
__device__ float    g_ed [HH * NN];
__device__ float    g_A1 [HH * NN];
__device__ float    g_A2 [HH * NN];
__device__ float    g_E1 [HH * NN];
__device__ float    g_E2 [HH * NN];
__device__ float    g_part[2 * NN * 512];        // j-split partial accumulators (16 MB)
__device__ float    g_zp  [2 * HH * NN];         // j-split partial Z

// ---------------- small helpers ----------------
__device__ __forceinline__ uint32_t f2tf(float x) {
    uint32_t r;
    asm("cvt.rna.tf32.f32 %0, %1;" : "=r"(r) : "f"(x));
    return r;
}

// 3xTF32 split: x ~= hi + lo, both tf32-representable
__device__ __forceinline__ void split_tf32(float x, uint32_t& hi, uint32_t& lo) {
    hi = f2tf(x);
    float r = x - __uint_as_float(hi);
    lo = f2tf(r);
}

__device__ __forceinline__ void mma_tf32(float c[4],
    const uint32_t a[4], uint32_t b0, uint32_t b1)
{
    asm volatile(
        "mma.sync.aligned.m16n8k8.row.col.f32.tf32.tf32.f32 "
        "{%0,%1,%2,%3}, {%4,%5,%6,%7}, {%8,%9}, {%0,%1,%2,%3};"
        : "+f"(c[0]), "+f"(c[1]), "+f"(c[2]), "+f"(c[3])
        : "r"(a[0]), "r"(a[1]), "r"(a[2]), "r"(a[3]), "r"(b0), "r"(b1));
}

// ---------------- pack adjacency to bitmask ----------------
__global__ void pack_adj_kernel(const int* __restrict__ adj, uint32_t* __restrict__ bits) {
    int row  = blockIdx.x;
    int warp = threadIdx.x >> 5;
    int lane = threadIdx.x & 31;
    for (int w = warp; w < NW; w += 32) {
        int v = adj[(size_t)row * NN + w * 32 + lane];
        unsigned m = __ballot_sync(0xffffffffu, v > 0);
        if (lane == 0) bits[row * NW + w] = m;
    }
}

// ---------------- 3xTF32 tensor-core GEMM: C[M,Nc] = A[M,K] @ B[K,Nc] (+bias) ----------------
__global__ void __launch_bounds__(256) gemm_tf32x3_kernel(
    const float* __restrict__ A, const float* __restrict__ B,
    const float* __restrict__ bias, float* __restrict__ C,
    int M, int Nc, int K)
{
    __shared__ uint32_t Ah[64 * 36], Al[64 * 36];
    __shared__ uint32_t Bh[32 * 72], Bl[32 * 72];

    const int tid  = threadIdx.x;
    const int lane = tid & 31, warp = tid >> 5;
    const int wm = warp & 1;
    const int wn = warp >> 1;
    const int m0 = blockIdx.y * 64, n0 = blockIdx.x * 64;

    float acc[2][2][4] = {};

    for (int k0 = 0; k0 < K; k0 += 32) {
        #pragma unroll
        for (int v = 0; v < 2; v++) {
            int idx = v * 256 + tid;     // 64 x 8 float4
            int m = idx >> 3, kv = idx & 7;
            float4 a = *(const float4*)&A[(size_t)(m0 + m) * K + k0 + kv * 4];
            uint4 uh, ul;
            split_tf32(a.x, uh.x, ul.x); split_tf32(a.y, uh.y, ul.y);
            split_tf32(a.z, uh.z, ul.z); split_tf32(a.w, uh.w, ul.w);
            *(uint4*)&Ah[m * 36 + kv * 4] = uh;
            *(uint4*)&Al[m * 36 + kv * 4] = ul;
        }
        #pragma unroll
        for (int v = 0; v < 2; v++) {
            int idx = v * 256 + tid;     // 32 x 16 float4
            int k = idx >> 4, nv = idx & 15;
            float4 b = *(const float4*)&B[(size_t)(k0 + k) * Nc + n0 + nv * 4];
            uint4 uh, ul;
            split_tf32(b.x, uh.x, ul.x); split_tf32(b.y, uh.y, ul.y);
            split_tf32(b.z, uh.z, ul.z); split_tf32(b.w, uh.w, ul.w);
            *(uint4*)&Bh[k * 72 + nv * 4] = uh;
            *(uint4*)&Bl[k * 72 + nv * 4] = ul;
        }
        __syncthreads();

        #pragma unroll
        for (int ks = 0; ks < 4; ks++) {
            const int kk = ks * 8;
            uint32_t ah[2][4], al[2][4];
            #pragma unroll
            for (int mt = 0; mt < 2; mt++) {
                int r = 32 * wm + 16 * mt + (lane >> 2);
                int c = kk + (lane & 3);
                ah[mt][0] = Ah[r * 36 + c];       al[mt][0] = Al[r * 36 + c];
                ah[mt][1] = Ah[(r + 8) * 36 + c]; al[mt][1] = Al[(r + 8) * 36 + c];
                ah[mt][2] = Ah[r * 36 + c + 4];   al[mt][2] = Al[r * 36 + c + 4];
                ah[mt][3] = Ah[(r + 8) * 36 + c + 4]; al[mt][3] = Al[(r + 8) * 36 + c + 4];
            }
            #pragma unroll
            for (int nt = 0; nt < 2; nt++) {
                int col = 16 * wn + 8 * nt + (lane >> 2);
                int ro  = (kk + (lane & 3)) * 72 + col;
                uint32_t bh0 = Bh[ro], bh1 = Bh[ro + 4 * 72];
                uint32_t bl0 = Bl[ro], bl1 = Bl[ro + 4 * 72];
                #pragma unroll
                for (int mt = 0; mt < 2; mt++) {
                    mma_tf32(acc[mt][nt], ah[mt], bh0, bh1);
                    mma_tf32(acc[mt][nt], ah[mt], bl0, bl1);
                    mma_tf32(acc[mt][nt], al[mt], bh0, bh1);
                }
            }
        }
        __syncthreads();
    }

    #pragma unroll
    for (int mt = 0; mt < 2; mt++) {
        #pragma unroll
        for (int nt = 0; nt < 2; nt++) {
            int col = n0 + 16 * wn + 8 * nt + 2 * (lane & 3);
            float bx = bias ? bias[col]     : 0.f;
            float by = bias ? bias[col + 1] : 0.f;
            int r0 = m0 + 32 * wm + 16 * mt + (lane >> 2);
            float2 o0 = make_float2(acc[mt][nt][0] + bx, acc[mt][nt][1] + by);
            float2 o1 = make_float2(acc[mt][nt][2] + bx, acc[mt][nt][3] + by);
            *(float2*)&C[(size_t)r0 * Nc + col]       = o0;
            *(float2*)&C[(size_t)(r0 + 8) * Nc + col] = o1;
        }
    }
}

// ---------------- scalar GEMM (final Nc=16) ----------------
__global__ void __launch_bounds__(256) gemm_kernel(
    const float* __restrict__ A, const float* __restrict__ B,
    const float* __restrict__ bias, float* __restrict__ C,
    int M, int Nc, int K)
{
    __shared__ float As[16][68];
    __shared__ float Bs[16][68];
    int tx = threadIdx.x & 15, ty = threadIdx.x >> 4;
    int m0 = blockIdx.y * 64, n0 = blockIdx.x * 64;
    float acc[4][4] = {};

    for (int k0 = 0; k0 < K; k0 += 16) {
        {
            int m  = threadIdx.x >> 2;
            int kv = threadIdx.x & 3;
            float4 a = *(const float4*)&A[(size_t)(m0 + m) * K + k0 + kv * 4];
            As[kv*4+0][m] = a.x; As[kv*4+1][m] = a.y;
            As[kv*4+2][m] = a.z; As[kv*4+3][m] = a.w;
        }
        {
            int k  = threadIdx.x >> 4;
            int nv = threadIdx.x & 15;
            int n  = n0 + nv * 4;
            float4 b = make_float4(0.f, 0.f, 0.f, 0.f);
            if (n < Nc) b = *(const float4*)&B[(size_t)(k0 + k) * Nc + n];
            *(float4*)&Bs[k][nv*4] = b;
        }
        __syncthreads();
        #pragma unroll
        for (int k = 0; k < 16; k++) {
            float4 a4 = *(const float4*)&As[k][ty*4];
            float4 b4 = *(const float4*)&Bs[k][tx*4];
            float av[4] = {a4.x, a4.y, a4.z, a4.w};
            float bv[4] = {b4.x, b4.y, b4.z, b4.w};
            #pragma unroll
            for (int i = 0; i < 4; i++)
                #pragma unroll
                for (int j = 0; j < 4; j++)
                    acc[i][j] += av[i] * bv[j];
        }
        __syncthreads();
    }
    int col = n0 + tx * 4;
    if (col < Nc) {
        float4 bv = make_float4(0.f,0.f,0.f,0.f);
        if (bias) bv = *(const float4*)&bias[col];
        #pragma unroll
        for (int i = 0; i < 4; i++) {
            int row = m0 + ty * 4 + i;
            float4 o;
            o.x = acc[i][0] + bv.x; o.y = acc[i][1] + bv.y;
            o.z = acc[i][2] + bv.z; o.w = acc[i][3] + bv.w;
            *(float4*)&C[(size_t)row * Nc + col] = o;
        }
    }
}

// ---------------- es/ed + exp factors (fused; unshifted exp is safe: |es+ed| <~ 9) ----------------
__global__ void esed_prep_kernel(const float* __restrict__ h,
                                 const float* __restrict__ as_, const float* __restrict__ ad_,
                                 float* __restrict__ es, float* __restrict__ ed,
                                 float* __restrict__ A1, float* __restrict__ A2,
                                 float* __restrict__ E1, float* __restrict__ E2, int F)
{
    int i = blockIdx.x;
    int w = threadIdx.x >> 5, lane = threadIdx.x & 31;
    float s = 0.f, d = 0.f;
    for (int f = lane; f < F; f += 32) {
        float hv = h[(size_t)i * (HH * F) + w * F + f];
        s += hv * as_[w * F + f];
        d += hv * ad_[w * F + f];
    }
    #pragma unroll
    for (int off = 16; off; off >>= 1) {
        s += __shfl_xor_sync(0xffffffffu, s, off);
        d += __shfl_xor_sync(0xffffffffu, d, off);
    }
    if (lane == 0) {
        int idx = w * NN + i;
        es[idx] = s;  ed[idx] = d;
        A1[idx] = expf(s);        A2[idx] = expf(0.2f * s);
        E1[idx] = expf(d);        E2[idx] = expf(0.2f * d);
    }
}

// ---------------- 2xTF32 double-buffered attention, j-split partial ----------------
// pacc[split][i][head*F+f] = sum_{j in split} w_ij h_jf ; pz[split][head][i] = sum w_ij
template<int F>
__global__ void __launch_bounds__(256) attn_tc3_kernel(
    const float* __restrict__ hbuf,          // [N][H*F]
    const uint32_t* __restrict__ adjbits,    // [N][NW]
    const float* __restrict__ es, const float* __restrict__ ed,
    const float* __restrict__ A1g, const float* __restrict__ A2g,
    const float* __restrict__ E1g, const float* __restrict__ E2g,
    float* __restrict__ pacc,                // [2][N][H*F]
    float* __restrict__ pz)                  // [2][H][N]
{
    constexpr int TI  = 64;
    constexpr int JB  = 32;
    constexpr int LDH = HH * F;
    constexpr int HS  = F + 8;
    constexpr int WS  = 36;
    constexpr int NT  = F / 32;
    constexpr int NV  = JB * F / 1024;
    constexpr int NB  = (NN / 2) / JB;       // 64 j-blocks per split

    const int head  = blockIdx.y;
    const int split = blockIdx.z;
    const int jbase = split * (NN / 2);
    const int i0    = blockIdx.x * TI;
    const int tid   = threadIdx.x;
    const int lane  = tid & 31, warp = tid >> 5;
    const int wm    = warp & 1;
    const int wn    = warp >> 1;

    extern __shared__ uint32_t smdyn[];
    uint32_t* h_hi = smdyn;                    // [2][JB*HS]
    uint32_t* w_hi = h_hi + 2 * JB * HS;       // [2][TI*WS]
    uint32_t* w_lo = w_hi + 2 * TI * WS;       // [2][TI*WS]
    float* es_s = (float*)(w_lo + 2 * TI * WS);
    float* A1_s = es_s + TI;
    float* A2_s = A1_s + TI;
    float* z_s  = A2_s + TI;

    if (tid < TI) {
        es_s[tid] = es [head * NN + i0 + tid];
        A1_s[tid] = A1g[head * NN + i0 + tid];
        A2_s[tid] = A2g[head * NN + i0 + tid];
    }

    float acc[2][NT][4];
    #pragma unroll
    for (int mt = 0; mt < 2; mt++)
        #pragma unroll
        for (int nt = 0; nt < NT; nt++)
            #pragma unroll
            for (int q = 0; q < 4; q++) acc[mt][nt][q] = 0.f;

    float zpriv[8] = {0.f,0.f,0.f,0.f,0.f,0.f,0.f,0.f};
    const int r1base = warp * 8;

    // prefetch first j-block of this split
    float4 pre[NV];
    #pragma unroll
    for (int v = 0; v < NV; v++) {
        int idx = v * 256 + tid;
        int j   = jbase + idx / (F / 4);
        int f4  = idx % (F / 4);
        pre[v] = *(const float4*)&hbuf[(size_t)j * LDH + head * F + f4 * 4];
    }

    __syncthreads();

    for (int jb = 0; jb < NB; jb++) {
        const int cur = jb & 1;
        uint32_t* hh = h_hi + cur * JB * HS;
        uint32_t* wh = w_hi + cur * TI * WS;
        uint32_t* wl = w_lo + cur * TI * WS;

        #pragma unroll
        for (int v = 0; v < NV; v++) {
            int idx = v * 256 + tid;
            int j   = idx / (F / 4);
            int f4  = idx % (F / 4);
            uint4 uh = make_uint4(f2tf(pre[v].x), f2tf(pre[v].y),
                                  f2tf(pre[v].z), f2tf(pre[v].w));
            *(uint4*)&hh[j * HS + f4 * 4] = uh;
        }
        {
            int jg = jbase + jb * JB + lane;
            int wword = (jbase >> 5) + jb;       // word index within the adjacency row
            float edv = ed [head * NN + jg];
            float e1  = E1g[head * NN + jg];
            float e2  = E2g[head * NN + jg];
            #pragma unroll
            for (int k = 0; k < 8; k++) {
                int r = r1base + k;
                uint32_t word = adjbits[(size_t)(i0 + r) * NW + wword];
                float s = es_s[r] + edv;
                float w = (s >= 0.f) ? A1_s[r] * e1 : A2_s[r] * e2;
                w = ((word >> lane) & 1u) ? w : 0.f;
                zpriv[k] += w;
                uint32_t whi, wlo;
                split_tf32(w, whi, wlo);
                wh[r * WS + lane] = whi;
                wl[r * WS + lane] = wlo;
            }
        }
        __syncthreads();

        if (jb + 1 < NB) {
            #pragma unroll
            for (int v = 0; v < NV; v++) {
                int idx = v * 256 + tid;
                int j   = jbase + (jb + 1) * JB + idx / (F / 4);
                int f4  = idx % (F / 4);
                pre[v] = *(const float4*)&hbuf[(size_t)j * LDH + head * F + f4 * 4];
            }
        }

        #pragma unroll
        for (int ks = 0; ks < 4; ks++) {
            const int kk = ks * 8;
            uint32_t ah[2][4], al[2][4];
            #pragma unroll
            for (int mt = 0; mt < 2; mt++) {
                int r = 32 * wm + 16 * mt + (lane >> 2);
                int c = kk + (lane & 3);
                ah[mt][0] = wh[r * WS + c];       al[mt][0] = wl[r * WS + c];
                ah[mt][1] = wh[(r + 8) * WS + c]; al[mt][1] = wl[(r + 8) * WS + c];
                ah[mt][2] = wh[r * WS + c + 4];   al[mt][2] = wl[r * WS + c + 4];
                ah[mt][3] = wh[(r + 8) * WS + c + 4]; al[mt][3] = wl[(r + 8) * WS + c + 4];
            }
            #pragma unroll
            for (int nt = 0; nt < NT; nt++) {
                int col = wn * 8 * NT + 8 * nt + (lane >> 2);
                int ro  = (kk + (lane & 3)) * HS + col;
                uint32_t bh0 = hh[ro], bh1 = hh[ro + 4 * HS];
                #pragma unroll
                for (int mt = 0; mt < 2; mt++) {
                    mma_tf32(acc[mt][nt], ah[mt], bh0, bh1);
                    mma_tf32(acc[mt][nt], al[mt], bh0, bh1);
                }
            }
        }
    }

    // Z reduction
    #pragma unroll
    for (int k = 0; k < 8; k++) {
        float z = zpriv[k];
        #pragma unroll
        for (int off = 16; off; off >>= 1) z += __shfl_xor_sync(0xffffffffu, z, off);
        if (lane == 0) z_s[r1base + k] = z;
    }
    __syncthreads();

    if (tid < TI)
        pz[(size_t)split * HH * NN + head * NN + i0 + tid] = z_s[tid];

    // epilogue: store raw partial accumulators
    float* po = pacc + (size_t)split * NN * LDH;
    #pragma unroll
    for (int mt = 0; mt < 2; mt++) {
        int r0 = 32 * wm + 16 * mt + (lane >> 2);
        int r1 = r0 + 8;
        #pragma unroll
        for (int nt = 0; nt < NT; nt++) {
            int col = wn * 8 * NT + 8 * nt + 2 * (lane & 3);
            float2 o0 = make_float2(acc[mt][nt][0], acc[mt][nt][1]);
            float2 o1 = make_float2(acc[mt][nt][2], acc[mt][nt][3]);
            *(float2*)&po[(size_t)(i0 + r0) * LDH + head * F + col] = o0;
            *(float2*)&po[(size_t)(i0 + r1) * LDH + head * F + col] = o1;
        }
    }
}

// ---------------- combine: out = (p0+p1)/(z0+z1) ----------------
template<int F>
__global__ void combine_kernel(const float* __restrict__ p, const float* __restrict__ z,
                               float* __restrict__ out)
{
    constexpr int LDH = HH * F;
    int idx = blockIdx.x * blockDim.x + threadIdx.x;      // float4 index over [NN][LDH/4]
    int row = idx / (LDH / 4);
    int c   = (idx % (LDH / 4)) * 4;
    int head = c / F;
    float zi = 1.f / (z[head * NN + row] + z[HH * NN + head * NN + row]);
    float4 a = *(const float4*)&p[(size_t)row * LDH + c];
    float4 b = *(const float4*)&p[(size_t)NN * LDH + (size_t)row * LDH + c];
    float4 o;
    o.x = (a.x + b.x) * zi; o.y = (a.y + b.y) * zi;
    o.z = (a.z + b.z) * zi; o.w = (a.w + b.w) * zi;
    *(float4*)&out[(size_t)row * LDH + c] = o;
}

// ---------------- BatchNorm (over rows) + ELU ----------------
__global__ void bnelu_kernel(const float* __restrict__ X,
                             const float* __restrict__ gamma, const float* __restrict__ beta,
                             float* __restrict__ Y, int C)
{
    int c = blockIdx.x;
    int t = threadIdx.x;
    float v[16];
    float s = 0.f, sq = 0.f;
    #pragma unroll
    for (int k = 0; k < 16; k++) {
        float x = X[(size_t)(t + k * 256) * C + c];
        v[k] = x; s += x; sq += x * x;
    }
    __shared__ float rs[256], rq[256];
    rs[t] = s; rq[t] = sq; __syncthreads();
    for (int o = 128; o; o >>= 1) {
        if (t < o) { rs[t] += rs[t + o]; rq[t] += rq[t + o]; }
        __syncthreads();
    }
    float mean = rs[0] * (1.f / NN);
    float var  = rq[0] * (1.f / NN) - mean * mean;
    float scale = rsqrtf(var + 1e-5f);
    float gm = gamma[c], bt = beta[c];
    #pragma unroll
    for (int k = 0; k < 16; k++) {
        float y = (v[k] - mean) * scale * gm + bt;
        y = (y > 0.f) ? y : expm1f(y);
        Y[(size_t)(t + k * 256) * C + c] = y;
    }
}

// ---------------- host ----------------
static inline void* sym(const void* s) { void* p = nullptr; cudaGetSymbolAddress(&p, s); return p; }

static constexpr int ATTN_SMEM_128 = (2*32*(128+8) + 2*2*64*36 + 4*64) * 4; // 72704 B
static constexpr int ATTN_SMEM_32  = (2*32*(32+8)  + 2*2*64*36 + 4*64) * 4; // 48128 B

extern "C" void kernel_launch(void* const* d_in, const int* in_sizes, int n_in,
                              void* d_out, int out_size)
{
    const float* x   = (const float*)d_in[0];
    const int*   adj = (const int*)  d_in[1];
    const float* W1  = (const float*)d_in[2];
    const float* a1s = (const float*)d_in[3];
    const float* a1d = (const float*)d_in[4];
    const float* lw1 = (const float*)d_in[5];
    const float* lb1 = (const float*)d_in[6];
    const float* g1  = (const float*)d_in[7];
    const float* be1 = (const float*)d_in[8];
    const float* W2  = (const float*)d_in[9];
    const float* a2s = (const float*)d_in[10];
    const float* a2d = (const float*)d_in[11];
    const float* lw2 = (const float*)d_in[12];
    const float* lb2 = (const float*)d_in[13];
    const float* g2  = (const float*)d_in[14];
    const float* be2 = (const float*)d_in[15];
    float* outp = (float*)d_out;

    uint32_t* adjbits = (uint32_t*)sym(g_adjbits);
    float* h1 = (float*)sym(g_h1);
    float* x1 = (float*)sym(g_x1);
    float* t1 = (float*)sym(g_t1);
    float* x2 = (float*)sym(g_x2);
    float* h2 = (float*)sym(g_h2);
    float* x3 = (float*)sym(g_x3);
    float* t2 = (float*)sym(g_t2);
    float* es = (float*)sym(g_es);
    float* ed = (float*)sym(g_ed);
    float* A1 = (float*)sym(g_A1);
    float* A2 = (float*)sym(g_A2);
    float* E1 = (float*)sym(g_E1);
    float* E2 = (float*)sym(g_E2);
    float* part = (float*)sym(g_part);
    float* zp   = (float*)sym(g_zp);

    cudaFuncSetAttribute(attn_tc3_kernel<128>,
                         cudaFuncAttributeMaxDynamicSharedMemorySize, ATTN_SMEM_128);
    cudaFuncSetAttribute(attn_tc3_kernel<32>,
                         cudaFuncAttributeMaxDynamicSharedMemorySize, ATTN_SMEM_32);

    pack_adj_kernel<<<NN, 1024>>>(adj, adjbits);

    // ----- layer 1 -----
    gemm_tf32x3_kernel<<<dim3(512/64, NN/64), 256>>>(x, W1, nullptr, h1, NN, 512, 512);
    esed_prep_kernel<<<NN, 128>>>(h1, a1s, a1d, es, ed, A1, A2, E1, E2, 128);
    attn_tc3_kernel<128><<<dim3(NN/64, HH, 2), 256, ATTN_SMEM_128>>>(
        h1, adjbits, es, ed, A1, A2, E1, E2, part, zp);
    combine_kernel<128><<<NN * 512 / 4 / 256, 256>>>(part, zp, x1);

    gemm_tf32x3_kernel<<<dim3(1, NN/64), 256>>>(x1, lw1, lb1, t1, NN, 64, 512);
    bnelu_kernel<<<64, 256>>>(t1, g1, be1, x2, 64);

    // ----- layer 2 -----
    gemm_tf32x3_kernel<<<dim3(2, NN/64), 256>>>(x2, W2, nullptr, h2, NN, 128, 64);
    esed_prep_kernel<<<NN, 128>>>(h2, a2s, a2d, es, ed, A1, A2, E1, E2, 32);
    attn_tc3_kernel<32><<<dim3(NN/64, HH, 2), 256, ATTN_SMEM_32>>>(
        h2, adjbits, es, ed, A1, A2, E1, E2, part, zp);
    combine_kernel<32><<<NN * 128 / 4 / 256, 256>>>(part, zp, x3);

    gemm_kernel<<<dim3(1, NN/64), 256>>>(x3, lw2, lb2, t2, NN, 16, 128);
    bnelu_kernel<<<16, 256>>>(t2, g2, be2, outp, 16);
}

// round 16
// speedup vs baseline: 1.5191x; 1.0130x over previous
#include <cuda_runtime.h>
#include <cuda_bf16.h>
#include <math.h>
#include <stdint.h>

#define NN   4096
#define HH   4
#define NW   (NN/32)     // 128 words per adjacency row

// ---------------- device scratch ----------------
__device__ uint32_t g_adjbits[NN * NW];          // 2 MB packed adjacency
__device__ float    g_h1 [NN * 512];             // x @ W1
__device__ float    g_x1 [NN * 512];             // GAT1 out
__device__ float    g_t1 [NN * 64];              // x1 @ lw1 + b
__device__ float    g_x2 [NN * 64];              // bn_elu
__device__ float    g_h2 [NN * 128];             // x2 @ W2
__device__ float    g_x3 [NN * 128];             // GAT2 out
__device__ float    g_t2 [NN * 16];              // x3 @ lw2 + b
__device__ float    g_es [HH * NN];
__device__ float    g_ed [HH * NN];
__device__ float    g_A1 [HH * NN];
__device__ float    g_A2 [HH * NN];
__device__ float    g_E1 [HH * NN];
__device__ float    g_E2 [HH * NN];
__device__ float    g_part[2 * NN * 512];        // j-split partial accumulators (16 MB)
__device__ float    g_zp  [2 * HH * NN];         // j-split partial Z

// ---------------- small helpers ----------------
__device__ __forceinline__ uint32_t f2tf(float x) {
    uint32_t r;
    asm("cvt.rna.tf32.f32 %0, %1;" : "=r"(r) : "f"(x));
    return r;
}

// 3xTF32 split: x ~= hi + lo, both tf32-representable
__device__ __forceinline__ void split_tf32(float x, uint32_t& hi, uint32_t& lo) {
    hi = f2tf(x);
    float r = x - __uint_as_float(hi);
    lo = f2tf(r);
}

__device__ __forceinline__ void mma_tf32(float c[4],
    const uint32_t a[4], uint32_t b0, uint32_t b1)
{
    asm volatile(
        "mma.sync.aligned.m16n8k8.row.col.f32.tf32.tf32.f32 "
        "{%0,%1,%2,%3}, {%4,%5,%6,%7}, {%8,%9}, {%0,%1,%2,%3};"
        : "+f"(c[0]), "+f"(c[1]), "+f"(c[2]), "+f"(c[3])
        : "r"(a[0]), "r"(a[1]), "r"(a[2]), "r"(a[3]), "r"(b0), "r"(b1));
}

__device__ __forceinline__ void cp_async16(uint32_t smem_addr, const void* gptr) {
    asm volatile("cp.async.cg.shared.global [%0], [%1], 16;"
                 :: "r"(smem_addr), "l"(gptr));
}
#define CP_COMMIT() asm volatile("cp.async.commit_group;" ::: "memory")
#define CP_WAIT0()  asm volatile("cp.async.wait_group 0;" ::: "memory")

// ---------------- pack adjacency to bitmask ----------------
__global__ void pack_adj_kernel(const int* __restrict__ adj, uint32_t* __restrict__ bits) {
    int row  = blockIdx.x;
    int warp = threadIdx.x >> 5;
    int lane = threadIdx.x & 31;
    for (int w = warp; w < NW; w += 32) {
        int v = adj[(size_t)row * NN + w * 32 + lane];
        unsigned m = __ballot_sync(0xffffffffu, v > 0);
        if (lane == 0) bits[row * NW + w] = m;
    }
}

// ---------------- 3xTF32 tensor-core GEMM: C[M,Nc] = A[M,K] @ B[K,Nc] (+bias) ----------------
__global__ void __launch_bounds__(256) gemm_tf32x3_kernel(
    const float* __restrict__ A, const float* __restrict__ B,
    const float* __restrict__ bias, float* __restrict__ C,
    int M, int Nc, int K)
{
    __shared__ uint32_t Ah[64 * 36], Al[64 * 36];
    __shared__ uint32_t Bh[32 * 72], Bl[32 * 72];

    const int tid  = threadIdx.x;
    const int lane = tid & 31, warp = tid >> 5;
    const int wm = warp & 1;
    const int wn = warp >> 1;
    const int m0 = blockIdx.y * 64, n0 = blockIdx.x * 64;

    float acc[2][2][4] = {};

    for (int k0 = 0; k0 < K; k0 += 32) {
        #pragma unroll
        for (int v = 0; v < 2; v++) {
            int idx = v * 256 + tid;     // 64 x 8 float4
            int m = idx >> 3, kv = idx & 7;
            float4 a = *(const float4*)&A[(size_t)(m0 + m) * K + k0 + kv * 4];
            uint4 uh, ul;
            split_tf32(a.x, uh.x, ul.x); split_tf32(a.y, uh.y, ul.y);
            split_tf32(a.z, uh.z, ul.z); split_tf32(a.w, uh.w, ul.w);
            *(uint4*)&Ah[m * 36 + kv * 4] = uh;
            *(uint4*)&Al[m * 36 + kv * 4] = ul;
        }
        #pragma unroll
        for (int v = 0; v < 2; v++) {
            int idx = v * 256 + tid;     // 32 x 16 float4
            int k = idx >> 4, nv = idx & 15;
            float4 b = *(const float4*)&B[(size_t)(k0 + k) * Nc + n0 + nv * 4];
            uint4 uh, ul;
            split_tf32(b.x, uh.x, ul.x); split_tf32(b.y, uh.y, ul.y);
            split_tf32(b.z, uh.z, ul.z); split_tf32(b.w, uh.w, ul.w);
            *(uint4*)&Bh[k * 72 + nv * 4] = uh;
            *(uint4*)&Bl[k * 72 + nv * 4] = ul;
        }
        __syncthreads();

        #pragma unroll
        for (int ks = 0; ks < 4; ks++) {
            const int kk = ks * 8;
            uint32_t ah[2][4], al[2][4];
            #pragma unroll
            for (int mt = 0; mt < 2; mt++) {
                int r = 32 * wm + 16 * mt + (lane >> 2);
                int c = kk + (lane & 3);
                ah[mt][0] = Ah[r * 36 + c];       al[mt][0] = Al[r * 36 + c];
                ah[mt][1] = Ah[(r + 8) * 36 + c]; al[mt][1] = Al[(r + 8) * 36 + c];
                ah[mt][2] = Ah[r * 36 + c + 4];   al[mt][2] = Al[r * 36 + c + 4];
                ah[mt][3] = Ah[(r + 8) * 36 + c + 4]; al[mt][3] = Al[(r + 8) * 36 + c + 4];
            }
            #pragma unroll
            for (int nt = 0; nt < 2; nt++) {
                int col = 16 * wn + 8 * nt + (lane >> 2);
                int ro  = (kk + (lane & 3)) * 72 + col;
                uint32_t bh0 = Bh[ro], bh1 = Bh[ro + 4 * 72];
                uint32_t bl0 = Bl[ro], bl1 = Bl[ro + 4 * 72];
                #pragma unroll
                for (int mt = 0; mt < 2; mt++) {
                    mma_tf32(acc[mt][nt], ah[mt], bh0, bh1);
                    mma_tf32(acc[mt][nt], ah[mt], bl0, bl1);
                    mma_tf32(acc[mt][nt], al[mt], bh0, bh1);
                }
            }
        }
        __syncthreads();
    }

    #pragma unroll
    for (int mt = 0; mt < 2; mt++) {
        #pragma unroll
        for (int nt = 0; nt < 2; nt++) {
            int col = n0 + 16 * wn + 8 * nt + 2 * (lane & 3);
            float bx = bias ? bias[col]     : 0.f;
            float by = bias ? bias[col + 1] : 0.f;
            int r0 = m0 + 32 * wm + 16 * mt + (lane >> 2);
            float2 o0 = make_float2(acc[mt][nt][0] + bx, acc[mt][nt][1] + by);
            float2 o1 = make_float2(acc[mt][nt][2] + bx, acc[mt][nt][3] + by);
            *(float2*)&C[(size_t)r0 * Nc + col]       = o0;
            *(float2*)&C[(size_t)(r0 + 8) * Nc + col] = o1;
        }
    }
}

// ---------------- scalar GEMM (final Nc=16) ----------------
__global__ void __launch_bounds__(256) gemm_kernel(
    const float* __restrict__ A, const float* __restrict__ B,
    const float* __restrict__ bias, float* __restrict__ C,
    int M, int Nc, int K)
{
    __shared__ float As[16][68];
    __shared__ float Bs[16][68];
    int tx = threadIdx.x & 15, ty = threadIdx.x >> 4;
    int m0 = blockIdx.y * 64, n0 = blockIdx.x * 64;
    float acc[4][4] = {};

    for (int k0 = 0; k0 < K; k0 += 16) {
        {
            int m  = threadIdx.x >> 2;
            int kv = threadIdx.x & 3;
            float4 a = *(const float4*)&A[(size_t)(m0 + m) * K + k0 + kv * 4];
            As[kv*4+0][m] = a.x; As[kv*4+1][m] = a.y;
            As[kv*4+2][m] = a.z; As[kv*4+3][m] = a.w;
        }
        {
            int k  = threadIdx.x >> 4;
            int nv = threadIdx.x & 15;
            int n  = n0 + nv * 4;
            float4 b = make_float4(0.f, 0.f, 0.f, 0.f);
            if (n < Nc) b = *(const float4*)&B[(size_t)(k0 + k) * Nc + n];
            *(float4*)&Bs[k][nv*4] = b;
        }
        __syncthreads();
        #pragma unroll
        for (int k = 0; k < 16; k++) {
            float4 a4 = *(const float4*)&As[k][ty*4];
            float4 b4 = *(const float4*)&Bs[k][tx*4];
            float av[4] = {a4.x, a4.y, a4.z, a4.w};
            float bv[4] = {b4.x, b4.y, b4.z, b4.w};
            #pragma unroll
            for (int i = 0; i < 4; i++)
                #pragma unroll
                for (int j = 0; j < 4; j++)
                    acc[i][j] += av[i] * bv[j];
        }
        __syncthreads();
    }
    int col = n0 + tx * 4;
    if (col < Nc) {
        float4 bv = make_float4(0.f,0.f,0.f,0.f);
        if (bias) bv = *(const float4*)&bias[col];
        #pragma unroll
        for (int i = 0; i < 4; i++) {
            int row = m0 + ty * 4 + i;
            float4 o;
            o.x = acc[i][0] + bv.x; o.y = acc[i][1] + bv.y;
            o.z = acc[i][2] + bv.z; o.w = acc[i][3] + bv.w;
            *(float4*)&C[(size_t)row * Nc + col] = o;
        }
    }
}

// ---------------- es/ed + exp factors (fused; unshifted exp is safe: |es+ed| <~ 9) ----------------
__global__ void esed_prep_kernel(const float* __restrict__ h,
                                 const float* __restrict__ as_, const float* __restrict__ ad_,
                                 float* __restrict__ es, float* __restrict__ ed,
                                 float* __restrict__ A1, float* __restrict__ A2,
                                 float* __restrict__ E1, float* __restrict__ E2, int F)
{
    int i = blockIdx.x;
    int w = threadIdx.x >> 5, lane = threadIdx.x & 31;
    float s = 0.f, d = 0.f;
    for (int f = lane; f < F; f += 32) {
        float hv = h[(size_t)i * (HH * F) + w * F + f];
        s += hv * as_[w * F + f];
        d += hv * ad_[w * F + f];
    }
    #pragma unroll
    for (int off = 16; off; off >>= 1) {
        s += __shfl_xor_sync(0xffffffffu, s, off);
        d += __shfl_xor_sync(0xffffffffu, d, off);
    }
    if (lane == 0) {
        int idx = w * NN + i;
        es[idx] = s;  ed[idx] = d;
        A1[idx] = expf(s);        A2[idx] = expf(0.2f * s);
        E1[idx] = expf(d);        E2[idx] = expf(0.2f * d);
    }
}

// ---------------- 2xTF32 attention, cp.async-staged h, j-split partial ----------------
// pacc[split][i][head*F+f] = sum_{j in split} w_ij h_jf ; pz[split][head][i] = sum w_ij
// h staged RAW via cp.async; cvt.rna to tf32 at B-fragment load. w split (exact).
template<int F>
__global__ void __launch_bounds__(256, 3) attn_tc3_kernel(
    const float* __restrict__ hbuf,          // [N][H*F]
    const uint32_t* __restrict__ adjbits,    // [N][NW]
    const float* __restrict__ es, const float* __restrict__ ed,
    const float* __restrict__ A1g, const float* __restrict__ A2g,
    const float* __restrict__ E1g, const float* __restrict__ E2g,
    float* __restrict__ pacc,                // [2][N][H*F]
    float* __restrict__ pz)                  // [2][H][N]
{
    constexpr int TI  = 64;
    constexpr int JB  = 32;
    constexpr int LDH = HH * F;
    constexpr int HS  = F + 8;
    constexpr int WS  = 36;
    constexpr int NT  = F / 32;
    constexpr int NV  = JB * F / 1024;       // 16B chunks per thread per h tile (4 or 1)
    constexpr int NB  = (NN / 2) / JB;       // 64 j-blocks per split

    const int head  = blockIdx.y;
    const int split = blockIdx.z;
    const int jbase = split * (NN / 2);
    const int i0    = blockIdx.x * TI;
    const int tid   = threadIdx.x;
    const int lane  = tid & 31, warp = tid >> 5;
    const int wm    = warp & 1;
    const int wn    = warp >> 1;

    extern __shared__ uint32_t smdyn[];
    uint32_t* h_hi = smdyn;                    // [2][JB*HS]  raw f32 bits
    uint32_t* w_hi = h_hi + 2 * JB * HS;       // [2][TI*WS]
    uint32_t* w_lo = w_hi + 2 * TI * WS;       // [2][TI*WS]
    float* es_s = (float*)(w_lo + 2 * TI * WS);
    float* A1_s = es_s + TI;
    float* A2_s = A1_s + TI;
    float* z_s  = A2_s + TI;

    if (tid < TI) {
        es_s[tid] = es [head * NN + i0 + tid];
        A1_s[tid] = A1g[head * NN + i0 + tid];
        A2_s[tid] = A2g[head * NN + i0 + tid];
    }

    float acc[2][NT][4];
    #pragma unroll
    for (int mt = 0; mt < 2; mt++)
        #pragma unroll
        for (int nt = 0; nt < NT; nt++)
            #pragma unroll
            for (int q = 0; q < 4; q++) acc[mt][nt][q] = 0.f;

    float zpriv[8] = {0.f,0.f,0.f,0.f,0.f,0.f,0.f,0.f};
    const int r1base = warp * 8;

    // prologue: async-stage j-block 0 into buffer 0 (raw f32)
    #pragma unroll
    for (int v = 0; v < NV; v++) {
        int idx = v * 256 + tid;
        int j   = idx / (F / 4);
        int f4  = idx % (F / 4);
        uint32_t dst = (uint32_t)__cvta_generic_to_shared(&h_hi[j * HS + f4 * 4]);
        cp_async16(dst, &hbuf[(size_t)(jbase + j) * LDH + head * F + f4 * 4]);
    }
    CP_COMMIT();

    __syncthreads();   // es_s/A1_s/A2_s visible

    for (int jb = 0; jb < NB; jb++) {
        const int cur = jb & 1;
        uint32_t* hh = h_hi + cur * JB * HS;
        uint32_t* wh = w_hi + cur * TI * WS;
        uint32_t* wl = w_lo + cur * TI * WS;

        // build w tile [TI][JB]; thread column j=lane, 8 rows per warp
        {
            int jg = jbase + jb * JB + lane;
            int wword = (jbase >> 5) + jb;
            float edv = ed [head * NN + jg];
            float e1  = E1g[head * NN + jg];
            float e2  = E2g[head * NN + jg];
            #pragma unroll
            for (int k = 0; k < 8; k++) {
                int r = r1base + k;
                uint32_t word = adjbits[(size_t)(i0 + r) * NW + wword];
                float s = es_s[r] + edv;
                float w = (s >= 0.f) ? A1_s[r] * e1 : A2_s[r] * e2;
                w = ((word >> lane) & 1u) ? w : 0.f;
                zpriv[k] += w;
                uint32_t whi, wlo;
                split_tf32(w, whi, wlo);
                wh[r * WS + lane] = whi;
                wl[r * WS + lane] = wlo;
            }
        }
        CP_WAIT0();        // h tile [cur] fully arrived (this thread's view)
        __syncthreads();   // all warps: w[cur] + h[cur] ready; MMA(jb-1) on buf[cur^1] done

        // async-stage next j-block into buffer cur^1 (safe: MMA(jb-1) complete)
        if (jb + 1 < NB) {
            uint32_t* hn = h_hi + (cur ^ 1) * JB * HS;
            #pragma unroll
            for (int v = 0; v < NV; v++) {
                int idx = v * 256 + tid;
                int j   = idx / (F / 4);
                int f4  = idx % (F / 4);
                uint32_t dst = (uint32_t)__cvta_generic_to_shared(&hn[j * HS + f4 * 4]);
                cp_async16(dst, &hbuf[(size_t)(jbase + (jb + 1) * JB + j) * LDH + head * F + f4 * 4]);
            }
            CP_COMMIT();
        }

        // C += (w_hi + w_lo) @ tf32(h) via 2 MMAs per k-step
        #pragma unroll
        for (int ks = 0; ks < 4; ks++) {
            const int kk = ks * 8;
            uint32_t ah[2][4], al[2][4];
            #pragma unroll
            for (int mt = 0; mt < 2; mt++) {
                int r = 32 * wm + 16 * mt + (lane >> 2);
                int c = kk + (lane & 3);
                ah[mt][0] = wh[r * WS + c];       al[mt][0] = wl[r * WS + c];
                ah[mt][1] = wh[(r + 8) * WS + c]; al[mt][1] = wl[(r + 8) * WS + c];
                ah[mt][2] = wh[r * WS + c + 4];   al[mt][2] = wl[r * WS + c + 4];
                ah[mt][3] = wh[(r + 8) * WS + c + 4]; al[mt][3] = wl[(r + 8) * WS + c + 4];
            }
            #pragma unroll
            for (int nt = 0; nt < NT; nt++) {
                int col = wn * 8 * NT + 8 * nt + (lane >> 2);
                int ro  = (kk + (lane & 3)) * HS + col;
                uint32_t bh0 = f2tf(__uint_as_float(hh[ro]));
                uint32_t bh1 = f2tf(__uint_as_float(hh[ro + 4 * HS]));
                #pragma unroll
                for (int mt = 0; mt < 2; mt++) {
                    mma_tf32(acc[mt][nt], ah[mt], bh0, bh1);
                    mma_tf32(acc[mt][nt], al[mt], bh0, bh1);
                }
            }
        }
    }

    // Z reduction
    #pragma unroll
    for (int k = 0; k < 8; k++) {
        float z = zpriv[k];
        #pragma unroll
        for (int off = 16; off; off >>= 1) z += __shfl_xor_sync(0xffffffffu, z, off);
        if (lane == 0) z_s[r1base + k] = z;
    }
    __syncthreads();

    if (tid < TI)
        pz[(size_t)split * HH * NN + head * NN + i0 + tid] = z_s[tid];

    // epilogue: store raw partial accumulators
    float* po = pacc + (size_t)split * NN * LDH;
    #pragma unroll
    for (int mt = 0; mt < 2; mt++) {
        int r0 = 32 * wm + 16 * mt + (lane >> 2);
        int r1 = r0 + 8;
        #pragma unroll
        for (int nt = 0; nt < NT; nt++) {
            int col = wn * 8 * NT + 8 * nt + 2 * (lane & 3);
            float2 o0 = make_float2(acc[mt][nt][0], acc[mt][nt][1]);
            float2 o1 = make_float2(acc[mt][nt][2], acc[mt][nt][3]);
            *(float2*)&po[(size_t)(i0 + r0) * LDH + head * F + col] = o0;
            *(float2*)&po[(size_t)(i0 + r1) * LDH + head * F + col] = o1;
        }
    }
}

// ---------------- combine: out = (p0+p1)/(z0+z1) ----------------
template<int F>
__global__ void combine_kernel(const float* __restrict__ p, const float* __restrict__ z,
                               float* __restrict__ out)
{
    constexpr int LDH = HH * F;
    int idx = blockIdx.x * blockDim.x + threadIdx.x;      // float4 index over [NN][LDH/4]
    int row = idx / (LDH / 4);
    int c   = (idx % (LDH / 4)) * 4;
    int head = c / F;
    float zi = 1.f / (z[head * NN + row] + z[HH * NN + head * NN + row]);
    float4 a = *(const float4*)&p[(size_t)row * LDH + c];
    float4 b = *(const float4*)&p[(size_t)NN * LDH + (size_t)row * LDH + c];
    float4 o;
    o.x = (a.x + b.x) * zi; o.y = (a.y + b.y) * zi;
    o.z = (a.z + b.z) * zi; o.w = (a.w + b.w) * zi;
    *(float4*)&out[(size_t)row * LDH + c] = o;
}

// ---------------- BatchNorm (over rows) + ELU ----------------
__global__ void bnelu_kernel(const float* __restrict__ X,
                             const float* __restrict__ gamma, const float* __restrict__ beta,
                             float* __restrict__ Y, int C)
{
    int c = blockIdx.x;
    int t = threadIdx.x;
    float v[16];
    float s = 0.f, sq = 0.f;
    #pragma unroll
    for (int k = 0; k < 16; k++) {
        float x = X[(size_t)(t + k * 256) * C + c];
        v[k] = x; s += x; sq += x * x;
    }
    __shared__ float rs[256], rq[256];
    rs[t] = s; rq[t] = sq; __syncthreads();
    for (int o = 128; o; o >>= 1) {
        if (t < o) { rs[t] += rs[t + o]; rq[t] += rq[t + o]; }
        __syncthreads();
    }
    float mean = rs[0] * (1.f / NN);
    float var  = rq[0] * (1.f / NN) - mean * mean;
    float scale = rsqrtf(var + 1e-5f);
    float gm = gamma[c], bt = beta[c];
    #pragma unroll
    for (int k = 0; k < 16; k++) {
        float y = (v[k] - mean) * scale * gm + bt;
        y = (y > 0.f) ? y : expm1f(y);
        Y[(size_t)(t + k * 256) * C + c] = y;
    }
}

// ---------------- host ----------------
static inline void* sym(const void* s) { void* p = nullptr; cudaGetSymbolAddress(&p, s); return p; }

static constexpr int ATTN_SMEM_128 = (2*32*(128+8) + 2*2*64*36 + 4*64) * 4; // 72704 B
static constexpr int ATTN_SMEM_32  = (2*32*(32+8)  + 2*2*64*36 + 4*64) * 4; // 48128 B

extern "C" void kernel_launch(void* const* d_in, const int* in_sizes, int n_in,
                              void* d_out, int out_size)
{
    const float* x   = (const float*)d_in[0];
    const int*   adj = (const int*)  d_in[1];
    const float* W1  = (const float*)d_in[2];
    const float* a1s = (const float*)d_in[3];
    const float* a1d = (const float*)d_in[4];
    const float* lw1 = (const float*)d_in[5];
    const float* lb1 = (const float*)d_in[6];
    const float* g1  = (const float*)d_in[7];
    const float* be1 = (const float*)d_in[8];
    const float* W2  = (const float*)d_in[9];
    const float* a2s = (const float*)d_in[10];
    const float* a2d = (const float*)d_in[11];
    const float* lw2 = (const float*)d_in[12];
    const float* lb2 = (const float*)d_in[13];
    const float* g2  = (const float*)d_in[14];
    const float* be2 = (const float*)d_in[15];
    float* outp = (float*)d_out;

    uint32_t* adjbits = (uint32_t*)sym(g_adjbits);
    float* h1 = (float*)sym(g_h1);
    float* x1 = (float*)sym(g_x1);
    float* t1 = (float*)sym(g_t1);
    float* x2 = (float*)sym(g_x2);
    float* h2 = (float*)sym(g_h2);
    float* x3 = (float*)sym(g_x3);
    float* t2 = (float*)sym(g_t2);
    float* es = (float*)sym(g_es);
    float* ed = (float*)sym(g_ed);
    float* A1 = (float*)sym(g_A1);
    float* A2 = (float*)sym(g_A2);
    float* E1 = (float*)sym(g_E1);
    float* E2 = (float*)sym(g_E2);
    float* part = (float*)sym(g_part);
    float* zp   = (float*)sym(g_zp);

    cudaFuncSetAttribute(attn_tc3_kernel<128>,
                         cudaFuncAttributeMaxDynamicSharedMemorySize, ATTN_SMEM_128);
    cudaFuncSetAttribute(attn_tc3_kernel<32>,
                         cudaFuncAttributeMaxDynamicSharedMemorySize, ATTN_SMEM_32);

    pack_adj_kernel<<<NN, 1024>>>(adj, adjbits);

    // ----- layer 1 -----
    gemm_tf32x3_kernel<<<dim3(512/64, NN/64), 256>>>(x, W1, nullptr, h1, NN, 512, 512);
    esed_prep_kernel<<<NN, 128>>>(h1, a1s, a1d, es, ed, A1, A2, E1, E2, 128);
    attn_tc3_kernel<128><<<dim3(NN/64, HH, 2), 256, ATTN_SMEM_128>>>(
        h1, adjbits, es, ed, A1, A2, E1, E2, part, zp);
    combine_kernel<128><<<NN * 512 / 4 / 256, 256>>>(part, zp, x1);

    gemm_tf32x3_kernel<<<dim3(1, NN/64), 256>>>(x1, lw1, lb1, t1, NN, 64, 512);
    bnelu_kernel<<<64, 256>>>(t1, g1, be1, x2, 64);

    // ----- layer 2 -----
    gemm_tf32x3_kernel<<<dim3(2, NN/64), 256>>>(x2, W2, nullptr, h2, NN, 128, 64);
    esed_prep_kernel<<<NN, 128>>>(h2, a2s, a2d, es, ed, A1, A2, E1, E2, 32);
    attn_tc3_kernel<32><<<dim3(NN/64, HH, 2), 256, ATTN_SMEM_32>>>(
        h2, adjbits, es, ed, A1, A2, E1, E2, part, zp);
    combine_kernel<32><<<NN * 128 / 4 / 256, 256>>>(part, zp, x3);

    gemm_kernel<<<dim3(1, NN/64), 256>>>(x3, lw2, lb2, t2, NN, 16, 128);
    bnelu_kernel<<<16, 256>>>(t2, g2, be2, outp, 16);
}